// round 13
// baseline (speedup 1.0000x reference)
#include <cuda_runtime.h>
#include <cuda_bf16.h>
#include <math.h>
#include <stdint.h>

#define HD  128
#define B_  128
#define NU_ 32
#define NT_ 64
#define P   272          // tile pitch bytes (136 bf16): conflict-free ldmatrix
#define PE  136
#define NTHR 512
#define HALF 17408       // half weight plane (64 k-rows x 272 B)

// ---------------- packed weights in static global scratch ----------------
__device__ __align__(16) __nv_bfloat16 g_w[13][2][HD * PE];

// ---------------- smem layout (byte offsets, 16B aligned) ----------------
#define OFF_B0    0          // 34816 = 2 half-buffers (chain A / comb hi)
#define OFF_B1    34816      // 34816 = 2 half-buffers (chain U / comb lo)
#define OFF_HU    69632      // 32-row tile hi
#define OFF_HU_L  78336      // 32-row tile lo
#define OFF_HA    87040      // 64-row tile hi
#define OFF_HA_L  104448
#define OFF_SA    121856     // chain-A scratch 64-row hi/lo
#define OFF_SA_L  139264
#define OFF_SU    156672     // chain-U scratch 64-row hi/lo
#define OFF_SU_L  174080
#define OFF_VA    191488     // 128 fp32 (round1 chainA mean / encoder mean)
#define OFF_VU    192000     // 128 fp32 (round1 chainU mean)
#define OFF_VA2   192512     // 128 fp32 (round2 aggr mean)
#define OFF_ANT   193024
#define OFF_FLG   193536     // 8 x int flags
#define OFF_TMA   193568     // 512: gmean partial (chain A)
#define OFF_TMU   194080     // 512: gmean partial (chain U)
#define SM_BYTES  194592

// ---------------- PTX helpers ----------------
__device__ __forceinline__ uint32_t smem_u32(const void* p) {
    uint32_t a;
    asm("{ .reg .u64 t; cvta.to.shared.u64 t, %1; cvt.u32.u64 %0, t; }"
        : "=r"(a) : "l"(p));
    return a;
}

#define LDSM4(d0, d1, d2, d3, a) \
    asm volatile("ldmatrix.sync.aligned.m8n8.x4.shared.b16 {%0,%1,%2,%3}, [%4];" \
                 : "=r"(d0), "=r"(d1), "=r"(d2), "=r"(d3) : "r"(a))
#define LDSM4T(d0, d1, d2, d3, a) \
    asm volatile("ldmatrix.sync.aligned.m8n8.x4.trans.shared.b16 {%0,%1,%2,%3}, [%4];" \
                 : "=r"(d0), "=r"(d1), "=r"(d2), "=r"(d3) : "r"(a))

#define MMA16816(c, a0, a1, a2, a3, b0, b1) \
    asm volatile("mma.sync.aligned.m16n8k16.row.col.f32.bf16.bf16.f32 " \
                 "{%0,%1,%2,%3}, {%4,%5,%6,%7}, {%8,%9}, {%0,%1,%2,%3};" \
                 : "+f"((c)[0]), "+f"((c)[1]), "+f"((c)[2]), "+f"((c)[3]) \
                 : "r"(a0), "r"(a1), "r"(a2), "r"(a3), "r"(b0), "r"(b1))

#define CP16(s, g) \
    asm volatile("cp.async.cg.shared.global [%0], [%1], 16;" :: "r"(s), "l"(g))
#define CP_COMMIT()  asm volatile("cp.async.commit_group;" ::: "memory")
#define CP_WAITG1()  asm volatile("cp.async.wait_group 1;" ::: "memory")
#define GBAR(id)     asm volatile("bar.sync %0, %1;" :: "r"(id), "r"(256) : "memory")

__device__ __forceinline__ float bget(const char* p) {
    return __bfloat162float(*(const __nv_bfloat16*)p);
}

__device__ __forceinline__ void put_split(char* hiT, char* loT, int m, int k, float v) {
    const __nv_bfloat16 h = __float2bfloat16(v);
    *(__nv_bfloat16*)(hiT + (size_t)m * P + k * 2) = h;
    *(__nv_bfloat16*)(loT + (size_t)m * P + k * 2) =
        __float2bfloat16(v - __bfloat162float(h));
}

__device__ __forceinline__ void raise_flag(volatile int* f) {
    __threadfence_block(); *f = 1;
}
__device__ __forceinline__ void wait_flag(volatile int* f) {
    while (*f == 0) {}
    __threadfence_block();
}

// ---------------- weight prep: fp32 W[k][n] -> padded bf16 hi/lo ----------------
__global__ __launch_bounds__(256) void prep_w(
    const float* __restrict__ ue,
    const float* __restrict__ caWa, const float* __restrict__ caWs,
    const float* __restrict__ caWc, const float* __restrict__ cuWa,
    const float* __restrict__ cuWs, const float* __restrict__ cuWc)
{
    const float* srcs[13] = {
        ue,
        caWa, caWa + 16384, caWs, caWs + 16384, caWc, caWc + 16384,
        cuWa, cuWa + 16384, cuWs, cuWs + 16384, cuWc, cuWc + 16384
    };
    const int w = blockIdx.x;
    const float* src = srcs[w];
    __nv_bfloat16* hi = &g_w[w][0][0];
    __nv_bfloat16* lo = &g_w[w][1][0];
    for (int idx = threadIdx.x; idx < HD * PE; idx += 256) {
        const int k = idx / PE;
        const int n = idx - k * PE;
        float v = (n < HD) ? __ldg(src + k * HD + n) : 0.f;
        const __nv_bfloat16 h = __float2bfloat16(v);
        hi[idx] = h;
        lo[idx] = __float2bfloat16(v - __bfloat162float(h));
    }
}

// ---------------- loaders ----------------
__device__ __forceinline__ void load_half256(uint32_t dst, const char* src, int gtid)
{
    #pragma unroll
    for (int i = 0; i < 5; i++) {
        const int e = gtid + i * 256;
        if (e < 1088) CP16(dst + e * 16, src + e * 16);
    }
    CP_COMMIT();
}

__device__ __forceinline__ void load_plane512(uint32_t dst, const char* src, int tid)
{
    #pragma unroll
    for (int i = 0; i < 5; i++) {
        const int e = tid + i * 512;
        if (e < 2176) CP16(dst + e * 16, src + e * 16);
    }
    CP_COMMIT();
}

// ---------------- full-plane passes (block-wide layers) ----------------
template<int MR, int NW>
__device__ __forceinline__ void mma_hi(uint32_t aHi, uint32_t aLo, uint32_t wPlane,
                                       float* acc, int gtid)
{
    constexpr int MT  = MR / 16;
    constexpr int NB  = NW / MT;
    constexpr int NNT = 16 / NB;
    const int lane = gtid & 31;
    const int wp   = gtid >> 5;
    const int mtg  = wp / NB;
    const int nb   = (wp % NB) * (NNT * 8);
    const int r8  = (lane & 7) + ((lane >> 3) & 1) * 8;
    const int g16 = lane >> 4;
    const uint32_t aH = aHi + (uint32_t)(mtg * 16 + r8) * P + g16 * 16;
    const uint32_t aL = aLo + (uint32_t)(mtg * 16 + r8) * P + g16 * 16;
    const uint32_t bB = wPlane + (uint32_t)r8 * P + (uint32_t)(nb + g16 * 8) * 2;

    #pragma unroll
    for (int kt = 0; kt < 8; kt++) {
        uint32_t bf[NNT / 2][4];
        #pragma unroll
        for (int np = 0; np < NNT / 2; np++)
            LDSM4T(bf[np][0], bf[np][1], bf[np][2], bf[np][3],
                   bB + kt * (16 * P) + np * 32);
        uint32_t ah0, ah1, ah2, ah3, al0, al1, al2, al3;
        LDSM4(ah0, ah1, ah2, ah3, aH + kt * 32);
        LDSM4(al0, al1, al2, al3, aL + kt * 32);
        #pragma unroll
        for (int np = 0; np < NNT / 2; np++) {
            MMA16816(acc + (2 * np) * 4,     ah0, ah1, ah2, ah3, bf[np][0], bf[np][1]);
            MMA16816(acc + (2 * np + 1) * 4, ah0, ah1, ah2, ah3, bf[np][2], bf[np][3]);
            MMA16816(acc + (2 * np) * 4,     al0, al1, al2, al3, bf[np][0], bf[np][1]);
            MMA16816(acc + (2 * np + 1) * 4, al0, al1, al2, al3, bf[np][2], bf[np][3]);
        }
    }
}

template<int MR, int NW>
__device__ __forceinline__ void mma_lo(uint32_t aHi, uint32_t wPlane,
                                       float* acc, int gtid)
{
    constexpr int MT  = MR / 16;
    constexpr int NB  = NW / MT;
    constexpr int NNT = 16 / NB;
    const int lane = gtid & 31;
    const int wp   = gtid >> 5;
    const int mtg  = wp / NB;
    const int nb   = (wp % NB) * (NNT * 8);
    const int r8  = (lane & 7) + ((lane >> 3) & 1) * 8;
    const int g16 = lane >> 4;
    const uint32_t aH = aHi + (uint32_t)(mtg * 16 + r8) * P + g16 * 16;
    const uint32_t bB = wPlane + (uint32_t)r8 * P + (uint32_t)(nb + g16 * 8) * 2;

    #pragma unroll
    for (int kt = 0; kt < 8; kt++) {
        uint32_t bf[NNT / 2][4];
        #pragma unroll
        for (int np = 0; np < NNT / 2; np++)
            LDSM4T(bf[np][0], bf[np][1], bf[np][2], bf[np][3],
                   bB + kt * (16 * P) + np * 32);
        uint32_t a0, a1, a2, a3;
        LDSM4(a0, a1, a2, a3, aH + kt * 32);
        #pragma unroll
        for (int np = 0; np < NNT / 2; np++) {
            MMA16816(acc + (2 * np) * 4,     a0, a1, a2, a3, bf[np][0], bf[np][1]);
            MMA16816(acc + (2 * np + 1) * 4, a0, a1, a2, a3, bf[np][2], bf[np][3]);
        }
    }
}

// ---------------- half-plane passes (chain layers, 8 warps) ----------------
template<int MR>
__device__ __forceinline__ void mma_half_hi(uint32_t aHi, uint32_t aLo, uint32_t wHalf,
                                            int kt0, float* acc, int gtid)
{
    constexpr int MT  = MR / 16;
    constexpr int NB  = 8 / MT;
    constexpr int NNT = 16 / NB;
    const int lane = gtid & 31;
    const int wp   = gtid >> 5;
    const int mtg  = wp / NB;
    const int nb   = (wp % NB) * (NNT * 8);
    const int r8  = (lane & 7) + ((lane >> 3) & 1) * 8;
    const int g16 = lane >> 4;
    const uint32_t aH = aHi + (uint32_t)(mtg * 16 + r8) * P + g16 * 16 + kt0 * 32;
    const uint32_t aL = aLo + (uint32_t)(mtg * 16 + r8) * P + g16 * 16 + kt0 * 32;
    const uint32_t bB = wHalf + (uint32_t)r8 * P + (uint32_t)(nb + g16 * 8) * 2;

    #pragma unroll
    for (int kt = 0; kt < 4; kt++) {
        uint32_t bf[NNT / 2][4];
        #pragma unroll
        for (int np = 0; np < NNT / 2; np++)
            LDSM4T(bf[np][0], bf[np][1], bf[np][2], bf[np][3],
                   bB + kt * (16 * P) + np * 32);
        uint32_t ah0, ah1, ah2, ah3, al0, al1, al2, al3;
        LDSM4(ah0, ah1, ah2, ah3, aH + kt * 32);
        LDSM4(al0, al1, al2, al3, aL + kt * 32);
        #pragma unroll
        for (int np = 0; np < NNT / 2; np++) {
            MMA16816(acc + (2 * np) * 4,     ah0, ah1, ah2, ah3, bf[np][0], bf[np][1]);
            MMA16816(acc + (2 * np + 1) * 4, ah0, ah1, ah2, ah3, bf[np][2], bf[np][3]);
            MMA16816(acc + (2 * np) * 4,     al0, al1, al2, al3, bf[np][0], bf[np][1]);
            MMA16816(acc + (2 * np + 1) * 4, al0, al1, al2, al3, bf[np][2], bf[np][3]);
        }
    }
}

template<int MR>
__device__ __forceinline__ void mma_half_lo(uint32_t aHi, uint32_t wHalf,
                                            int kt0, float* acc, int gtid)
{
    constexpr int MT  = MR / 16;
    constexpr int NB  = 8 / MT;
    constexpr int NNT = 16 / NB;
    const int lane = gtid & 31;
    const int wp   = gtid >> 5;
    const int mtg  = wp / NB;
    const int nb   = (wp % NB) * (NNT * 8);
    const int r8  = (lane & 7) + ((lane >> 3) & 1) * 8;
    const int g16 = lane >> 4;
    const uint32_t aH = aHi + (uint32_t)(mtg * 16 + r8) * P + g16 * 16 + kt0 * 32;
    const uint32_t bB = wHalf + (uint32_t)r8 * P + (uint32_t)(nb + g16 * 8) * 2;

    #pragma unroll
    for (int kt = 0; kt < 4; kt++) {
        uint32_t bf[NNT / 2][4];
        #pragma unroll
        for (int np = 0; np < NNT / 2; np++)
            LDSM4T(bf[np][0], bf[np][1], bf[np][2], bf[np][3],
                   bB + kt * (16 * P) + np * 32);
        uint32_t a0, a1, a2, a3;
        LDSM4(a0, a1, a2, a3, aH + kt * 32);
        #pragma unroll
        for (int np = 0; np < NNT / 2; np++) {
            MMA16816(acc + (2 * np) * 4,     a0, a1, a2, a3, bf[np][0], bf[np][1]);
            MMA16816(acc + (2 * np + 1) * 4, a0, a1, a2, a3, bf[np][2], bf[np][3]);
        }
    }
}

// ---------------- epilogue: bias + relu (+vec) -> split bf16 tiles ----------------
template<int MR, int NW>
__device__ __forceinline__ void epilogue_t(const float* acc,
    char* oHi, char* oLo, const float* __restrict__ bias, const float* addv, int gtid)
{
    constexpr int MT  = MR / 16;
    constexpr int NB  = NW / MT;
    constexpr int NNT = 16 / NB;
    const int lane = gtid & 31;
    const int wp   = gtid >> 5;
    const int mtg  = wp / NB;
    const int nb   = (wp % NB) * (NNT * 8);
    const int r0   = mtg * 16 + (lane >> 2);

    #pragma unroll
    for (int t = 0; t < NNT; t++) {
        const int c0 = nb + t * 8 + (lane & 3) * 2;
        const float b0v = __ldg(bias + c0), b1v = __ldg(bias + c0 + 1);
        float av0 = 0.f, av1 = 0.f;
        if (addv) { av0 = addv[c0]; av1 = addv[c0 + 1]; }
        const float y0 = fmaxf(acc[t * 4 + 0] + b0v, 0.f) + av0;
        const float y1 = fmaxf(acc[t * 4 + 1] + b1v, 0.f) + av1;
        const float y2 = fmaxf(acc[t * 4 + 2] + b0v, 0.f) + av0;
        const float y3 = fmaxf(acc[t * 4 + 3] + b1v, 0.f) + av1;

        __nv_bfloat162 h01, h23, l01, l23;
        h01.x = __float2bfloat16(y0); h01.y = __float2bfloat16(y1);
        h23.x = __float2bfloat16(y2); h23.y = __float2bfloat16(y3);
        l01.x = __float2bfloat16(y0 - __bfloat162float(h01.x));
        l01.y = __float2bfloat16(y1 - __bfloat162float(h01.y));
        l23.x = __float2bfloat16(y2 - __bfloat162float(h23.x));
        l23.y = __float2bfloat16(y3 - __bfloat162float(h23.y));

        *(__nv_bfloat162*)(oHi + (size_t)r0 * P + c0 * 2)       = h01;
        *(__nv_bfloat162*)(oHi + (size_t)(r0 + 8) * P + c0 * 2) = h23;
        *(__nv_bfloat162*)(oLo + (size_t)r0 * P + c0 * 2)       = l01;
        *(__nv_bfloat162*)(oLo + (size_t)(r0 + 8) * P + c0 * 2) = l23;
    }
}

// ---------------- chain (8-warp) layer with half-plane pipelining ----------------
template<int MR>
__device__ __forceinline__ void glayer(
    int barid, int gtid, int widx, int widx_next,
    uint32_t aHi, uint32_t aLo, char* oHi, char* oLo,
    const float* bias, const float* addv,
    volatile int* waitflag, volatile int* raiseflag,
    uint32_t buf0, uint32_t buf1)
{
    constexpr int NNT = 16 / (8 / (MR / 16));
    float acc[NNT * 4];
    #pragma unroll
    for (int i = 0; i < NNT * 4; i++) acc[i] = 0.f;

    const char* wlo = (const char*)&g_w[widx][1][0];

    CP_WAITG1(); GBAR(barid);                        // hi.h0 ready
    mma_half_hi<MR>(aHi, aLo, buf0, 0, acc, gtid);
    GBAR(barid);
    load_half256(buf0, wlo, gtid);
    CP_WAITG1(); GBAR(barid);                        // hi.h1 ready
    mma_half_hi<MR>(aHi, aLo, buf1, 4, acc, gtid);
    GBAR(barid);
    load_half256(buf1, wlo + HALF, gtid);
    CP_WAITG1(); GBAR(barid);                        // lo.h0 ready
    mma_half_lo<MR>(aHi, buf0, 0, acc, gtid);
    GBAR(barid);
    if (widx_next >= 0)
        load_half256(buf0, (const char*)&g_w[widx_next][0][0], gtid);
    else CP_COMMIT();
    CP_WAITG1(); GBAR(barid);                        // lo.h1 ready
    mma_half_lo<MR>(aHi, buf1, 4, acc, gtid);
    GBAR(barid);                                     // all A/W reads done
    if (widx_next >= 0)
        load_half256(buf1, (const char*)&g_w[widx_next][0][0] + HALF, gtid);
    else CP_COMMIT();

    if (raiseflag) raise_flag(raiseflag);
    if (waitflag)  wait_flag(waitflag);
    epilogue_t<MR, 8>(acc, oHi, oLo, bias, addv, gtid);
    GBAR(barid);                                     // outputs visible in crew
}

// crew-parallel column mean of hi+lo tile -> vec[128]
__device__ __forceinline__ void gmean2(int barid, int gtid,
                                       const char* tHi, const char* tLo,
                                       int nrows, float* vec, float* tmp)
{
    const int c = gtid & 127;
    const char* t = (gtid < 128) ? tHi : tLo;
    float s = 0.f;
    for (int m = 0; m < nrows; m++)
        s += bget(t + (size_t)m * P + c * 2);
    if (gtid < 128) vec[c] = s; else tmp[c] = s;
    GBAR(barid);
    if (gtid < 128) vec[c] = (vec[c] + tmp[c]) / (float)nrows;
    GBAR(barid);
}

// block-serial column mean (encoder)
__device__ __forceinline__ void gmean(int gtid, const char* tHi, const char* tLo,
                                      int nrows, float* vec)
{
    if (gtid < HD) {
        float s = 0.f;
        for (int m = 0; m < nrows; m++)
            s += bget(tHi + (size_t)m * P + gtid * 2) +
                 bget(tLo + (size_t)m * P + gtid * 2);
        vec[gtid] = s / (float)nrows;
    }
}

// ---------------- block (16-warp) pipelined layer ----------------
template<int MR>
__device__ __forceinline__ void blayer(
    int tid, uint32_t bufHi, uint32_t bufLo,
    const char* pfHi, const char* pfLo,
    uint32_t aHi, uint32_t aLo, char* oHi, char* oLo,
    const float* bias, const float* addv)
{
    constexpr int NNT = 16 / (16 / (MR / 16));
    float acc[NNT * 4];
    #pragma unroll
    for (int i = 0; i < NNT * 4; i++) acc[i] = 0.f;

    CP_WAITG1(); __syncthreads();
    mma_hi<MR, 16>(aHi, aLo, bufHi, acc, tid);
    __syncthreads();
    if (pfHi) load_plane512(bufHi, pfHi, tid); else CP_COMMIT();
    CP_WAITG1(); __syncthreads();
    mma_lo<MR, 16>(aHi, bufLo, acc, tid);
    __syncthreads();
    if (pfLo) load_plane512(bufLo, pfLo, tid); else CP_COMMIT();
    epilogue_t<MR, 16>(acc, oHi, oLo, bias, addv, tid);
    __syncthreads();
}

// ---------------- chain runners: round 1 + round 2 extension ----------------
// flags: f[0]=chainA read old HU done; f[1]=chainU read old HA done;
//        f[2]=vA2 ready; f[3]=HA_new ready; f[4]=HU_new ready
__device__ void chainA(int gtid, char* sm, uint32_t smb,
                       const float* caba, const float* cabs, const float* cabc,
                       volatile int* f, float* vA, float* vA2, float* tmpA)
{
    const uint32_t b0 = smb + OFF_B0;
    const uint32_t b1 = smb + OFF_B0 + HALF;
    load_half256(b0, (const char*)&g_w[1][0][0], gtid);
    load_half256(b1, (const char*)&g_w[1][0][0] + HALF, gtid);

    // round 1: na chain
    glayer<32>(1, gtid, 1, 2, smb + OFF_HU, smb + OFF_HU_L,
               sm + OFF_SA, sm + OFF_SA_L, caba, nullptr, nullptr, f + 0, b0, b1);
    glayer<32>(1, gtid, 2, 3, smb + OFF_SA, smb + OFF_SA_L,
               sm + OFF_SA, sm + OFF_SA_L, caba + 128, nullptr, nullptr, nullptr, b0, b1);
    gmean2(1, gtid, sm + OFF_SA, sm + OFF_SA_L, NU_, vA, tmpA);
    glayer<64>(1, gtid, 3, 4, smb + OFF_HA, smb + OFF_HA_L,
               sm + OFF_SA, sm + OFF_SA_L, cabs, nullptr, nullptr, nullptr, b0, b1);
    glayer<64>(1, gtid, 4, 5, smb + OFF_SA, smb + OFF_SA_L,
               sm + OFF_SA, sm + OFF_SA_L, cabs + 128, vA, nullptr, nullptr, b0, b1);
    glayer<64>(1, gtid, 5, 6, smb + OFF_SA, smb + OFF_SA_L,
               sm + OFF_SA, sm + OFF_SA_L, cabc, nullptr, nullptr, nullptr, b0, b1);
    glayer<64>(1, gtid, 6, 1, smb + OFF_SA, smb + OFF_SA_L,
               sm + OFF_HA, sm + OFF_HA_L, cabc + 128, nullptr, f + 1, nullptr, b0, b1);
    raise_flag(f + 3);                       // HA_new ready

    // round 2: aggr MLP on hu_new (produced by chainU)
    wait_flag(f + 4);                        // HU_new ready
    glayer<32>(1, gtid, 1, 2, smb + OFF_HU, smb + OFF_HU_L,
               sm + OFF_SA, sm + OFF_SA_L, caba, nullptr, nullptr, nullptr, b0, b1);
    glayer<32>(1, gtid, 2, -1, smb + OFF_SA, smb + OFF_SA_L,
               sm + OFF_SA, sm + OFF_SA_L, caba + 128, nullptr, nullptr, nullptr, b0, b1);
    gmean2(1, gtid, sm + OFF_SA, sm + OFF_SA_L, NU_, vA2, tmpA);
    raise_flag(f + 2);                       // vA2 ready
}

__device__ void chainU(int gtid, char* sm, uint32_t smb,
                       const float* cuba, const float* cubs, const float* cubc,
                       const float* cabs,
                       volatile int* f, float* vU, float* vA2, float* tmpU)
{
    const uint32_t b0 = smb + OFF_B1;
    const uint32_t b1 = smb + OFF_B1 + HALF;
    load_half256(b0, (const char*)&g_w[7][0][0], gtid);
    load_half256(b1, (const char*)&g_w[7][0][0] + HALF, gtid);

    // round 1: nu chain
    glayer<64>(2, gtid, 7, 8, smb + OFF_HA, smb + OFF_HA_L,
               sm + OFF_SU, sm + OFF_SU_L, cuba, nullptr, nullptr, f + 1, b0, b1);
    glayer<64>(2, gtid, 8, 9, smb + OFF_SU, smb + OFF_SU_L,
               sm + OFF_SU, sm + OFF_SU_L, cuba + 128, nullptr, nullptr, nullptr, b0, b1);
    gmean2(2, gtid, sm + OFF_SU, sm + OFF_SU_L, NT_, vU, tmpU);
    glayer<32>(2, gtid, 9, 10, smb + OFF_HU, smb + OFF_HU_L,
               sm + OFF_SU, sm + OFF_SU_L, cubs, nullptr, nullptr, nullptr, b0, b1);
    glayer<32>(2, gtid, 10, 11, smb + OFF_SU, smb + OFF_SU_L,
               sm + OFF_SU, sm + OFF_SU_L, cubs + 128, vU, nullptr, nullptr, b0, b1);
    glayer<32>(2, gtid, 11, 12, smb + OFF_SU, smb + OFF_SU_L,
               sm + OFF_SU, sm + OFF_SU_L, cubc, nullptr, nullptr, nullptr, b0, b1);
    glayer<32>(2, gtid, 12, 3, smb + OFF_SU, smb + OFF_SU_L,
               sm + OFF_HU, sm + OFF_HU_L, cubc + 128, nullptr, f + 0, nullptr, b0, b1);
    raise_flag(f + 4);                       // HU_new ready

    // round 2: self MLP on ha_new (produced by chainA)
    wait_flag(f + 3);                        // HA_new ready
    glayer<64>(2, gtid, 3, 4, smb + OFF_HA, smb + OFF_HA_L,
               sm + OFF_SU, sm + OFF_SU_L, cabs, nullptr, nullptr, nullptr, b0, b1);
    // s2 epilogue needs vA2: wait on f[2] at the pre-epilogue slot
    glayer<64>(2, gtid, 4, -1, smb + OFF_SU, smb + OFF_SU_L,
               sm + OFF_SU, sm + OFF_SU_L, cabs + 128, vA2, f + 2, nullptr, b0, b1);
}

// ---------------- main fused kernel ----------------
__global__ __launch_bounds__(NTHR, 1) void gnn_mma(
    const float* __restrict__ uf,   const float* __restrict__ noise,
    const float* __restrict__ b_ue,
    const float* __restrict__ W_t,  const float* __restrict__ b_t,
    const float* __restrict__ caba, const float* __restrict__ cabs,
    const float* __restrict__ cabc, const float* __restrict__ cuba,
    const float* __restrict__ cubs, const float* __restrict__ cubc,
    const float* __restrict__ Wn,   const float* __restrict__ bn,
    float* __restrict__ out)
{
    extern __shared__ __align__(16) char sm[];
    const uint32_t smb = smem_u32(sm);
    const int tid = threadIdx.x;
    const int b   = blockIdx.x;

    float* vA   = (float*)(sm + OFF_VA);
    float* vU   = (float*)(sm + OFF_VU);
    float* vA2  = (float*)(sm + OFF_VA2);
    float* ant  = (float*)(sm + OFF_ANT);
    float* tmpA = (float*)(sm + OFF_TMA);
    float* tmpU = (float*)(sm + OFF_TMU);
    volatile int* flg = (volatile int*)(sm + OFF_FLG);

    if (tid < 8) flg[tid] = 0;

    // ---------- encoder ----------
    {
        const float* src = uf + (size_t)b * NU_ * HD;
        for (int idx = tid; idx < NU_ * HD; idx += NTHR) {
            const int m = idx >> 7, k = idx & 127;
            put_split(sm + OFF_SA, sm + OFF_SA_L, m, k, __ldg(src + idx));
        }
    }
    load_plane512(smb + OFF_B0, (const char*)&g_w[0][0][0], tid);
    load_plane512(smb + OFF_B1, (const char*)&g_w[0][1][0], tid);
    __syncthreads();   // staging + flag init visible
    blayer<32>(tid, smb + OFF_B0, smb + OFF_B1, nullptr, nullptr,
               smb + OFF_SA, smb + OFF_SA_L, sm + OFF_HU, sm + OFF_HU_L,
               b_ue, nullptr);

    // ant = relu(mean_u(hu) @ W_t + b_t)
    gmean(tid, sm + OFF_HU, sm + OFF_HU_L, NU_, vA);
    __syncthreads();
    if (tid < HD) {
        float acc = __ldg(b_t + tid);
        #pragma unroll 8
        for (int k = 0; k < HD; k++)
            acc += vA[k] * __ldg(W_t + k * HD + tid);
        ant[tid] = fmaxf(acc, 0.f);
    }
    __syncthreads();
    {   // HA = split(ant + noise)
        const float* np_ = noise + (size_t)b * NT_ * HD;
        for (int idx = tid; idx < NT_ * HD; idx += NTHR) {
            const int m = idx >> 7, f = idx & 127;
            put_split(sm + OFF_HA, sm + OFF_HA_L, m, f, ant[f] + __ldg(np_ + idx));
        }
    }
    __syncthreads();

    // ---------- round 1 + round 2 aggr/self: two concurrent chains ----------
    if (tid < 256)
        chainA(tid, sm, smb, caba, cabs, cabc, flg, vA, vA2, tmpA);
    else
        chainU(tid - 256, sm, smb, cuba, cubs, cubc, cabs, flg, vU, vA2, tmpU);
    __syncthreads();

    // ---------- round 2 comb: block-wide (2 x M64) ----------
    load_plane512(smb + OFF_B0, (const char*)&g_w[5][0][0], tid);   // w5 hi
    load_plane512(smb + OFF_B1, (const char*)&g_w[5][1][0], tid);   // w5 lo
    blayer<64>(tid, smb + OFF_B0, smb + OFF_B1,
               (const char*)&g_w[6][0][0], (const char*)&g_w[6][1][0],
               smb + OFF_SU, smb + OFF_SU_L, sm + OFF_SU, sm + OFF_SU_L,
               cabc, nullptr);
    blayer<64>(tid, smb + OFF_B0, smb + OFF_B1, nullptr, nullptr,
               smb + OFF_SU, smb + OFF_SU_L, sm + OFF_SU, sm + OFF_SU_L,
               cabc + 128, nullptr);

    // ---------- final projection + complex-pair normalization ----------
    float* TAf  = (float*)(sm + OFF_B0);          // [64][128] fp32
    float* WnS  = (float*)(sm + OFF_B1);          // [128][16]
    float* nbuf = (float*)(sm + OFF_B1 + 8192);   // [64][16]
    for (int idx = tid; idx < NT_ * HD; idx += NTHR) {
        const int m = idx >> 7, k = idx & 127;
        TAf[idx] = bget(sm + OFF_SU   + (size_t)m * P + k * 2) +
                   bget(sm + OFF_SU_L + (size_t)m * P + k * 2);
    }
    for (int i = tid; i < HD * 16; i += NTHR) WnS[i] = __ldg(Wn + i);
    __syncthreads();

    const int c  = tid & 15;
    const int rb = tid >> 4;      // 0..31
    float yv[2];
    #pragma unroll
    for (int i = 0; i < 2; i++) {
        const int r = rb + 32 * i;
        float acc = __ldg(bn + c);
        #pragma unroll 8
        for (int k = 0; k < HD; k++)
            acc += TAf[r * HD + k] * WnS[k * 16 + c];
        nbuf[r * 16 + c] = acc;
        yv[i] = acc;
    }
    __syncthreads();
    #pragma unroll
    for (int i = 0; i < 2; i++) {
        const int r  = rb + 32 * i;
        const int cp = c & 7;
        const float re  = nbuf[r * 16 + cp];
        const float im  = nbuf[r * 16 + cp + 8];
        const float mag = sqrtf(re * re + im * im);
        out[((size_t)b * NT_ + r) * 16 + c] = yv[i] / mag;
    }
}

// ---------------------------------------------------------------------
extern "C" void kernel_launch(void* const* d_in, const int* in_sizes, int n_in,
                              void* d_out, int out_size)
{
    (void)in_sizes; (void)n_in; (void)out_size;

    const float* user_feat = (const float*)d_in[0];
    const float* ant_noise = (const float*)d_in[1];
    // d_in[2..5]: edge indices — deterministic full bipartite per batch; unused.
    const float* W_ue = (const float*)d_in[6];
    const float* b_ue = (const float*)d_in[7];
    const float* W_t  = (const float*)d_in[8];
    const float* b_t  = (const float*)d_in[9];
    const float* caWa = (const float*)d_in[10];
    const float* caba = (const float*)d_in[11];
    const float* caWs = (const float*)d_in[12];
    const float* cabs = (const float*)d_in[13];
    const float* caWc = (const float*)d_in[14];
    const float* cabc = (const float*)d_in[15];
    const float* cuWa = (const float*)d_in[16];
    const float* cuba = (const float*)d_in[17];
    const float* cuWs = (const float*)d_in[18];
    const float* cubs = (const float*)d_in[19];
    const float* cuWc = (const float*)d_in[20];
    const float* cubc = (const float*)d_in[21];
    const float* Wn   = (const float*)d_in[22];
    const float* bn   = (const float*)d_in[23];
    float* out = (float*)d_out;

    static int init_done = 0;
    if (!init_done) {
        cudaFuncSetAttribute(gnn_mma,
                             cudaFuncAttributeMaxDynamicSharedMemorySize,
                             SM_BYTES);
        init_done = 1;
    }

    prep_w<<<13, 256>>>(W_ue, caWa, caWs, caWc, cuWa, cuWs, cuWc);
    gnn_mma<<<B_, NTHR, SM_BYTES>>>(
        user_feat, ant_noise, b_ue, W_t, b_t,
        caba, cabs, cabc, cuba, cubs, cubc,
        Wn, bn, out);
}

// round 14
// speedup vs baseline: 1.0038x; 1.0038x over previous
#include <cuda_runtime.h>
#include <cuda_bf16.h>
#include <math.h>
#include <stdint.h>

#define HD  128
#define B_  128
#define NU_ 32
#define NT_ 64
#define P   272          // tile pitch bytes (136 bf16): conflict-free ldmatrix
#define PE  136
#define NTHR 512
#define HALF 17408       // half weight plane (64 k-rows x 272 B)

// ---------------- packed weights in static global scratch ----------------
__device__ __align__(16) __nv_bfloat16 g_w[13][2][HD * PE];

// ---------------- smem layout (byte offsets, 16B aligned) ----------------
#define OFF_B0    0          // 34816 = 2 half-buffers (chain A / comb hi)
#define OFF_B1    34816      // 34816 = 2 half-buffers (chain U / comb lo)
#define OFF_HU    69632      // 32-row tile hi
#define OFF_HU_L  78336      // 32-row tile lo
#define OFF_HA    87040      // 64-row tile hi
#define OFF_HA_L  104448
#define OFF_SA    121856     // chain-A scratch 64-row hi/lo
#define OFF_SA_L  139264
#define OFF_SU    156672     // chain-U scratch 64-row hi/lo
#define OFF_SU_L  174080
#define OFF_VA    191488     // 128 fp32
#define OFF_VU    192000
#define OFF_VA2   192512
#define OFF_ANT   193024
#define OFF_FLG   193536     // 8 x int flags
#define OFF_TMA   193568     // 512: gmean partial (chain A)
#define OFF_TMU   194080     // 512: gmean partial (chain U)
#define SM_BYTES  194592

// ---------------- PTX helpers ----------------
__device__ __forceinline__ uint32_t smem_u32(const void* p) {
    uint32_t a;
    asm("{ .reg .u64 t; cvta.to.shared.u64 t, %1; cvt.u32.u64 %0, t; }"
        : "=r"(a) : "l"(p));
    return a;
}

#define LDSM4(d0, d1, d2, d3, a) \
    asm volatile("ldmatrix.sync.aligned.m8n8.x4.shared.b16 {%0,%1,%2,%3}, [%4];" \
                 : "=r"(d0), "=r"(d1), "=r"(d2), "=r"(d3) : "r"(a))
#define LDSM4T(d0, d1, d2, d3, a) \
    asm volatile("ldmatrix.sync.aligned.m8n8.x4.trans.shared.b16 {%0,%1,%2,%3}, [%4];" \
                 : "=r"(d0), "=r"(d1), "=r"(d2), "=r"(d3) : "r"(a))

#define MMA16816(c, a0, a1, a2, a3, b0, b1) \
    asm volatile("mma.sync.aligned.m16n8k16.row.col.f32.bf16.bf16.f32 " \
                 "{%0,%1,%2,%3}, {%4,%5,%6,%7}, {%8,%9}, {%0,%1,%2,%3};" \
                 : "+f"((c)[0]), "+f"((c)[1]), "+f"((c)[2]), "+f"((c)[3]) \
                 : "r"(a0), "r"(a1), "r"(a2), "r"(a3), "r"(b0), "r"(b1))

#define CP16(s, g) \
    asm volatile("cp.async.cg.shared.global [%0], [%1], 16;" :: "r"(s), "l"(g))
#define CP_COMMIT()  asm volatile("cp.async.commit_group;" ::: "memory")
#define CP_WAITG1()  asm volatile("cp.async.wait_group 1;" ::: "memory")
#define GBAR(id)     asm volatile("bar.sync %0, %1;" :: "r"(id), "r"(256) : "memory")

__device__ __forceinline__ float bget(const char* p) {
    return __bfloat162float(*(const __nv_bfloat16*)p);
}

__device__ __forceinline__ void put_split(char* hiT, char* loT, int m, int k, float v) {
    const __nv_bfloat16 h = __float2bfloat16(v);
    *(__nv_bfloat16*)(hiT + (size_t)m * P + k * 2) = h;
    *(__nv_bfloat16*)(loT + (size_t)m * P + k * 2) =
        __float2bfloat16(v - __bfloat162float(h));
}

__device__ __forceinline__ void raise_flag(volatile int* f) {
    __threadfence_block(); *f = 1;
}
__device__ __forceinline__ void wait_flag(volatile int* f) {
    while (*f == 0) {}
    __threadfence_block();
}

// ---------------- weight prep: fp32 W[k][n] -> padded bf16 hi/lo ----------------
__global__ __launch_bounds__(256) void prep_w(
    const float* __restrict__ ue,
    const float* __restrict__ caWa, const float* __restrict__ caWs,
    const float* __restrict__ caWc, const float* __restrict__ cuWa,
    const float* __restrict__ cuWs, const float* __restrict__ cuWc)
{
    const float* srcs[13] = {
        ue,
        caWa, caWa + 16384, caWs, caWs + 16384, caWc, caWc + 16384,
        cuWa, cuWa + 16384, cuWs, cuWs + 16384, cuWc, cuWc + 16384
    };
    const int w = blockIdx.x;
    const float* src = srcs[w];
    __nv_bfloat16* hi = &g_w[w][0][0];
    __nv_bfloat16* lo = &g_w[w][1][0];
    for (int idx = threadIdx.x; idx < HD * PE; idx += 256) {
        const int k = idx / PE;
        const int n = idx - k * PE;
        float v = (n < HD) ? __ldg(src + k * HD + n) : 0.f;
        const __nv_bfloat16 h = __float2bfloat16(v);
        hi[idx] = h;
        lo[idx] = __float2bfloat16(v - __bfloat162float(h));
    }
}

// ---------------- loaders ----------------
__device__ __forceinline__ void load_half256(uint32_t dst, const char* src, int gtid)
{
    #pragma unroll
    for (int i = 0; i < 5; i++) {
        const int e = gtid + i * 256;
        if (e < 1088) CP16(dst + e * 16, src + e * 16);
    }
    CP_COMMIT();
}

__device__ __forceinline__ void load_plane512(uint32_t dst, const char* src, int tid)
{
    #pragma unroll
    for (int i = 0; i < 5; i++) {
        const int e = tid + i * 512;
        if (e < 2176) CP16(dst + e * 16, src + e * 16);
    }
    CP_COMMIT();
}

// ---------------- full-plane passes (block-wide layers) ----------------
// Reordered: all ah-MMAs over the full acc set, then all al-MMAs (max reuse distance)
template<int MR, int NW>
__device__ __forceinline__ void mma_hi(uint32_t aHi, uint32_t aLo, uint32_t wPlane,
                                       float* acc, int gtid)
{
    constexpr int MT  = MR / 16;
    constexpr int NB  = NW / MT;
    constexpr int NNT = 16 / NB;
    const int lane = gtid & 31;
    const int wp   = gtid >> 5;
    const int mtg  = wp / NB;
    const int nb   = (wp % NB) * (NNT * 8);
    const int r8  = (lane & 7) + ((lane >> 3) & 1) * 8;
    const int g16 = lane >> 4;
    const uint32_t aH = aHi + (uint32_t)(mtg * 16 + r8) * P + g16 * 16;
    const uint32_t aL = aLo + (uint32_t)(mtg * 16 + r8) * P + g16 * 16;
    const uint32_t bB = wPlane + (uint32_t)r8 * P + (uint32_t)(nb + g16 * 8) * 2;

    #pragma unroll
    for (int kt = 0; kt < 8; kt++) {
        uint32_t bf[NNT / 2][4];
        #pragma unroll
        for (int np = 0; np < NNT / 2; np++)
            LDSM4T(bf[np][0], bf[np][1], bf[np][2], bf[np][3],
                   bB + kt * (16 * P) + np * 32);
        uint32_t ah0, ah1, ah2, ah3, al0, al1, al2, al3;
        LDSM4(ah0, ah1, ah2, ah3, aH + kt * 32);
        LDSM4(al0, al1, al2, al3, aL + kt * 32);
        #pragma unroll
        for (int np = 0; np < NNT / 2; np++) {
            MMA16816(acc + (2 * np) * 4,     ah0, ah1, ah2, ah3, bf[np][0], bf[np][1]);
            MMA16816(acc + (2 * np + 1) * 4, ah0, ah1, ah2, ah3, bf[np][2], bf[np][3]);
        }
        #pragma unroll
        for (int np = 0; np < NNT / 2; np++) {
            MMA16816(acc + (2 * np) * 4,     al0, al1, al2, al3, bf[np][0], bf[np][1]);
            MMA16816(acc + (2 * np + 1) * 4, al0, al1, al2, al3, bf[np][2], bf[np][3]);
        }
    }
}

template<int MR, int NW>
__device__ __forceinline__ void mma_lo(uint32_t aHi, uint32_t wPlane,
                                       float* acc, int gtid)
{
    constexpr int MT  = MR / 16;
    constexpr int NB  = NW / MT;
    constexpr int NNT = 16 / NB;
    const int lane = gtid & 31;
    const int wp   = gtid >> 5;
    const int mtg  = wp / NB;
    const int nb   = (wp % NB) * (NNT * 8);
    const int r8  = (lane & 7) + ((lane >> 3) & 1) * 8;
    const int g16 = lane >> 4;
    const uint32_t aH = aHi + (uint32_t)(mtg * 16 + r8) * P + g16 * 16;
    const uint32_t bB = wPlane + (uint32_t)r8 * P + (uint32_t)(nb + g16 * 8) * 2;

    #pragma unroll
    for (int kt = 0; kt < 8; kt++) {
        uint32_t bf[NNT / 2][4];
        #pragma unroll
        for (int np = 0; np < NNT / 2; np++)
            LDSM4T(bf[np][0], bf[np][1], bf[np][2], bf[np][3],
                   bB + kt * (16 * P) + np * 32);
        uint32_t a0, a1, a2, a3;
        LDSM4(a0, a1, a2, a3, aH + kt * 32);
        #pragma unroll
        for (int np = 0; np < NNT / 2; np++) {
            MMA16816(acc + (2 * np) * 4,     a0, a1, a2, a3, bf[np][0], bf[np][1]);
            MMA16816(acc + (2 * np + 1) * 4, a0, a1, a2, a3, bf[np][2], bf[np][3]);
        }
    }
}

// ---------------- half-plane passes (chain layers, 8 warps) ----------------
template<int MR>
__device__ __forceinline__ void mma_half_hi(uint32_t aHi, uint32_t aLo, uint32_t wHalf,
                                            int kt0, float* acc, int gtid)
{
    constexpr int MT  = MR / 16;
    constexpr int NB  = 8 / MT;
    constexpr int NNT = 16 / NB;
    const int lane = gtid & 31;
    const int wp   = gtid >> 5;
    const int mtg  = wp / NB;
    const int nb   = (wp % NB) * (NNT * 8);
    const int r8  = (lane & 7) + ((lane >> 3) & 1) * 8;
    const int g16 = lane >> 4;
    const uint32_t aH = aHi + (uint32_t)(mtg * 16 + r8) * P + g16 * 16 + kt0 * 32;
    const uint32_t aL = aLo + (uint32_t)(mtg * 16 + r8) * P + g16 * 16 + kt0 * 32;
    const uint32_t bB = wHalf + (uint32_t)r8 * P + (uint32_t)(nb + g16 * 8) * 2;

    #pragma unroll
    for (int kt = 0; kt < 4; kt++) {
        uint32_t bf[NNT / 2][4];
        #pragma unroll
        for (int np = 0; np < NNT / 2; np++)
            LDSM4T(bf[np][0], bf[np][1], bf[np][2], bf[np][3],
                   bB + kt * (16 * P) + np * 32);
        uint32_t ah0, ah1, ah2, ah3, al0, al1, al2, al3;
        LDSM4(ah0, ah1, ah2, ah3, aH + kt * 32);
        LDSM4(al0, al1, al2, al3, aL + kt * 32);
        #pragma unroll
        for (int np = 0; np < NNT / 2; np++) {
            MMA16816(acc + (2 * np) * 4,     ah0, ah1, ah2, ah3, bf[np][0], bf[np][1]);
            MMA16816(acc + (2 * np + 1) * 4, ah0, ah1, ah2, ah3, bf[np][2], bf[np][3]);
        }
        #pragma unroll
        for (int np = 0; np < NNT / 2; np++) {
            MMA16816(acc + (2 * np) * 4,     al0, al1, al2, al3, bf[np][0], bf[np][1]);
            MMA16816(acc + (2 * np + 1) * 4, al0, al1, al2, al3, bf[np][2], bf[np][3]);
        }
    }
}

template<int MR>
__device__ __forceinline__ void mma_half_lo(uint32_t aHi, uint32_t wHalf,
                                            int kt0, float* acc, int gtid)
{
    constexpr int MT  = MR / 16;
    constexpr int NB  = 8 / MT;
    constexpr int NNT = 16 / NB;
    const int lane = gtid & 31;
    const int wp   = gtid >> 5;
    const int mtg  = wp / NB;
    const int nb   = (wp % NB) * (NNT * 8);
    const int r8  = (lane & 7) + ((lane >> 3) & 1) * 8;
    const int g16 = lane >> 4;
    const uint32_t aH = aHi + (uint32_t)(mtg * 16 + r8) * P + g16 * 16 + kt0 * 32;
    const uint32_t bB = wHalf + (uint32_t)r8 * P + (uint32_t)(nb + g16 * 8) * 2;

    #pragma unroll
    for (int kt = 0; kt < 4; kt++) {
        uint32_t bf[NNT / 2][4];
        #pragma unroll
        for (int np = 0; np < NNT / 2; np++)
            LDSM4T(bf[np][0], bf[np][1], bf[np][2], bf[np][3],
                   bB + kt * (16 * P) + np * 32);
        uint32_t a0, a1, a2, a3;
        LDSM4(a0, a1, a2, a3, aH + kt * 32);
        #pragma unroll
        for (int np = 0; np < NNT / 2; np++) {
            MMA16816(acc + (2 * np) * 4,     a0, a1, a2, a3, bf[np][0], bf[np][1]);
            MMA16816(acc + (2 * np + 1) * 4, a0, a1, a2, a3, bf[np][2], bf[np][3]);
        }
    }
}

// ---------------- epilogue: bias + relu (+vec) -> split bf16 tiles ----------------
template<int MR, int NW>
__device__ __forceinline__ void epilogue_t(const float* acc,
    char* oHi, char* oLo, const float* __restrict__ bias, const float* addv, int gtid)
{
    constexpr int MT  = MR / 16;
    constexpr int NB  = NW / MT;
    constexpr int NNT = 16 / NB;
    const int lane = gtid & 31;
    const int wp   = gtid >> 5;
    const int mtg  = wp / NB;
    const int nb   = (wp % NB) * (NNT * 8);
    const int r0   = mtg * 16 + (lane >> 2);

    #pragma unroll
    for (int t = 0; t < NNT; t++) {
        const int c0 = nb + t * 8 + (lane & 3) * 2;
        const float b0v = __ldg(bias + c0), b1v = __ldg(bias + c0 + 1);
        float av0 = 0.f, av1 = 0.f;
        if (addv) { av0 = addv[c0]; av1 = addv[c0 + 1]; }
        const float y0 = fmaxf(acc[t * 4 + 0] + b0v, 0.f) + av0;
        const float y1 = fmaxf(acc[t * 4 + 1] + b1v, 0.f) + av1;
        const float y2 = fmaxf(acc[t * 4 + 2] + b0v, 0.f) + av0;
        const float y3 = fmaxf(acc[t * 4 + 3] + b1v, 0.f) + av1;

        __nv_bfloat162 h01, h23, l01, l23;
        h01.x = __float2bfloat16(y0); h01.y = __float2bfloat16(y1);
        h23.x = __float2bfloat16(y2); h23.y = __float2bfloat16(y3);
        l01.x = __float2bfloat16(y0 - __bfloat162float(h01.x));
        l01.y = __float2bfloat16(y1 - __bfloat162float(h01.y));
        l23.x = __float2bfloat16(y2 - __bfloat162float(h23.x));
        l23.y = __float2bfloat16(y3 - __bfloat162float(h23.y));

        *(__nv_bfloat162*)(oHi + (size_t)r0 * P + c0 * 2)       = h01;
        *(__nv_bfloat162*)(oHi + (size_t)(r0 + 8) * P + c0 * 2) = h23;
        *(__nv_bfloat162*)(oLo + (size_t)r0 * P + c0 * 2)       = l01;
        *(__nv_bfloat162*)(oLo + (size_t)(r0 + 8) * P + c0 * 2) = l23;
    }
}

// ---------------- chain (8-warp) layer with half-plane pipelining ----------------
template<int MR>
__device__ __forceinline__ void glayer(
    int barid, int gtid, int widx, int widx_next,
    uint32_t aHi, uint32_t aLo, char* oHi, char* oLo,
    const float* bias, const float* addv,
    volatile int* waitflag, volatile int* raiseflag,
    uint32_t buf0, uint32_t buf1)
{
    constexpr int NNT = 16 / (8 / (MR / 16));
    float acc[NNT * 4];
    #pragma unroll
    for (int i = 0; i < NNT * 4; i++) acc[i] = 0.f;

    const char* wlo = (const char*)&g_w[widx][1][0];

    CP_WAITG1(); GBAR(barid);                        // hi.h0 ready
    mma_half_hi<MR>(aHi, aLo, buf0, 0, acc, gtid);
    GBAR(barid);
    load_half256(buf0, wlo, gtid);
    CP_WAITG1(); GBAR(barid);                        // hi.h1 ready
    mma_half_hi<MR>(aHi, aLo, buf1, 4, acc, gtid);
    GBAR(barid);
    load_half256(buf1, wlo + HALF, gtid);
    CP_WAITG1(); GBAR(barid);                        // lo.h0 ready
    mma_half_lo<MR>(aHi, buf0, 0, acc, gtid);
    GBAR(barid);
    if (widx_next >= 0)
        load_half256(buf0, (const char*)&g_w[widx_next][0][0], gtid);
    else CP_COMMIT();
    CP_WAITG1(); GBAR(barid);                        // lo.h1 ready
    mma_half_lo<MR>(aHi, buf1, 4, acc, gtid);
    GBAR(barid);                                     // all A/W reads done
    if (widx_next >= 0)
        load_half256(buf1, (const char*)&g_w[widx_next][0][0] + HALF, gtid);
    else CP_COMMIT();

    if (raiseflag) raise_flag(raiseflag);
    if (waitflag)  wait_flag(waitflag);
    epilogue_t<MR, 8>(acc, oHi, oLo, bias, addv, gtid);
    GBAR(barid);                                     // outputs visible in crew
}

// crew-parallel column mean of hi+lo tile -> vec[128]
__device__ __forceinline__ void gmean2(int barid, int gtid,
                                       const char* tHi, const char* tLo,
                                       int nrows, float* vec, float* tmp)
{
    const int c = gtid & 127;
    const char* t = (gtid < 128) ? tHi : tLo;
    float s = 0.f;
    for (int m = 0; m < nrows; m++)
        s += bget(t + (size_t)m * P + c * 2);
    if (gtid < 128) vec[c] = s; else tmp[c] = s;
    GBAR(barid);
    if (gtid < 128) vec[c] = (vec[c] + tmp[c]) / (float)nrows;
    GBAR(barid);
}

// block-serial column mean (encoder)
__device__ __forceinline__ void gmean(int gtid, const char* tHi, const char* tLo,
                                      int nrows, float* vec)
{
    if (gtid < HD) {
        float s = 0.f;
        for (int m = 0; m < nrows; m++)
            s += bget(tHi + (size_t)m * P + gtid * 2) +
                 bget(tLo + (size_t)m * P + gtid * 2);
        vec[gtid] = s / (float)nrows;
    }
}

// ---------------- block (16-warp) pipelined layer ----------------
template<int MR>
__device__ __forceinline__ void blayer(
    int tid, uint32_t bufHi, uint32_t bufLo,
    const char* pfHi, const char* pfLo,
    uint32_t aHi, uint32_t aLo, char* oHi, char* oLo,
    const float* bias, const float* addv)
{
    constexpr int NNT = 16 / (16 / (MR / 16));
    float acc[NNT * 4];
    #pragma unroll
    for (int i = 0; i < NNT * 4; i++) acc[i] = 0.f;

    CP_WAITG1(); __syncthreads();
    mma_hi<MR, 16>(aHi, aLo, bufHi, acc, tid);
    __syncthreads();
    if (pfHi) load_plane512(bufHi, pfHi, tid); else CP_COMMIT();
    CP_WAITG1(); __syncthreads();
    mma_lo<MR, 16>(aHi, bufLo, acc, tid);
    __syncthreads();
    if (pfLo) load_plane512(bufLo, pfLo, tid); else CP_COMMIT();
    epilogue_t<MR, 16>(acc, oHi, oLo, bias, addv, tid);
    __syncthreads();
}

// ---------------- chain runners: round 1 + round 2 extension ----------------
// flags: f[0]=chainA read old HU done; f[1]=chainU read old HA done;
//        f[2]=vA2 ready; f[3]=HA_new ready; f[4]=HU_new ready
__device__ void chainA(int gtid, char* sm, uint32_t smb,
                       const float* caba, const float* cabs, const float* cabc,
                       volatile int* f, float* vA, float* vA2, float* tmpA)
{
    const uint32_t b0 = smb + OFF_B0;
    const uint32_t b1 = smb + OFF_B0 + HALF;
    load_half256(b0, (const char*)&g_w[1][0][0], gtid);
    load_half256(b1, (const char*)&g_w[1][0][0] + HALF, gtid);

    // round 1: na chain
    glayer<32>(1, gtid, 1, 2, smb + OFF_HU, smb + OFF_HU_L,
               sm + OFF_SA, sm + OFF_SA_L, caba, nullptr, nullptr, f + 0, b0, b1);
    glayer<32>(1, gtid, 2, 3, smb + OFF_SA, smb + OFF_SA_L,
               sm + OFF_SA, sm + OFF_SA_L, caba + 128, nullptr, nullptr, nullptr, b0, b1);
    gmean2(1, gtid, sm + OFF_SA, sm + OFF_SA_L, NU_, vA, tmpA);
    glayer<64>(1, gtid, 3, 4, smb + OFF_HA, smb + OFF_HA_L,
               sm + OFF_SA, sm + OFF_SA_L, cabs, nullptr, nullptr, nullptr, b0, b1);
    glayer<64>(1, gtid, 4, 5, smb + OFF_SA, smb + OFF_SA_L,
               sm + OFF_SA, sm + OFF_SA_L, cabs + 128, vA, nullptr, nullptr, b0, b1);
    glayer<64>(1, gtid, 5, 6, smb + OFF_SA, smb + OFF_SA_L,
               sm + OFF_SA, sm + OFF_SA_L, cabc, nullptr, nullptr, nullptr, b0, b1);
    glayer<64>(1, gtid, 6, 1, smb + OFF_SA, smb + OFF_SA_L,
               sm + OFF_HA, sm + OFF_HA_L, cabc + 128, nullptr, f + 1, nullptr, b0, b1);
    raise_flag(f + 3);                       // HA_new ready

    // round 2: aggr MLP on hu_new (produced by chainU)
    wait_flag(f + 4);                        // HU_new ready
    glayer<32>(1, gtid, 1, 2, smb + OFF_HU, smb + OFF_HU_L,
               sm + OFF_SA, sm + OFF_SA_L, caba, nullptr, nullptr, nullptr, b0, b1);
    glayer<32>(1, gtid, 2, -1, smb + OFF_SA, smb + OFF_SA_L,
               sm + OFF_SA, sm + OFF_SA_L, caba + 128, nullptr, nullptr, nullptr, b0, b1);
    gmean2(1, gtid, sm + OFF_SA, sm + OFF_SA_L, NU_, vA2, tmpA);
    raise_flag(f + 2);                       // vA2 ready
}

__device__ void chainU(int gtid, char* sm, uint32_t smb,
                       const float* cuba, const float* cubs, const float* cubc,
                       const float* cabs,
                       volatile int* f, float* vU, float* vA2, float* tmpU)
{
    const uint32_t b0 = smb + OFF_B1;
    const uint32_t b1 = smb + OFF_B1 + HALF;
    load_half256(b0, (const char*)&g_w[7][0][0], gtid);
    load_half256(b1, (const char*)&g_w[7][0][0] + HALF, gtid);

    // round 1: nu chain
    glayer<64>(2, gtid, 7, 8, smb + OFF_HA, smb + OFF_HA_L,
               sm + OFF_SU, sm + OFF_SU_L, cuba, nullptr, nullptr, f + 1, b0, b1);
    glayer<64>(2, gtid, 8, 9, smb + OFF_SU, smb + OFF_SU_L,
               sm + OFF_SU, sm + OFF_SU_L, cuba + 128, nullptr, nullptr, nullptr, b0, b1);
    gmean2(2, gtid, sm + OFF_SU, sm + OFF_SU_L, NT_, vU, tmpU);
    glayer<32>(2, gtid, 9, 10, smb + OFF_HU, smb + OFF_HU_L,
               sm + OFF_SU, sm + OFF_SU_L, cubs, nullptr, nullptr, nullptr, b0, b1);
    glayer<32>(2, gtid, 10, 11, smb + OFF_SU, smb + OFF_SU_L,
               sm + OFF_SU, sm + OFF_SU_L, cubs + 128, vU, nullptr, nullptr, b0, b1);
    glayer<32>(2, gtid, 11, 12, smb + OFF_SU, smb + OFF_SU_L,
               sm + OFF_SU, sm + OFF_SU_L, cubc, nullptr, nullptr, nullptr, b0, b1);
    glayer<32>(2, gtid, 12, 3, smb + OFF_SU, smb + OFF_SU_L,
               sm + OFF_HU, sm + OFF_HU_L, cubc + 128, nullptr, f + 0, nullptr, b0, b1);
    raise_flag(f + 4);                       // HU_new ready

    // round 2: self MLP on ha_new (produced by chainA)
    wait_flag(f + 3);                        // HA_new ready
    glayer<64>(2, gtid, 3, 4, smb + OFF_HA, smb + OFF_HA_L,
               sm + OFF_SU, sm + OFF_SU_L, cabs, nullptr, nullptr, nullptr, b0, b1);
    glayer<64>(2, gtid, 4, -1, smb + OFF_SU, smb + OFF_SU_L,
               sm + OFF_SU, sm + OFF_SU_L, cabs + 128, vA2, f + 2, nullptr, b0, b1);
}

// ---------------- main fused kernel ----------------
__global__ __launch_bounds__(NTHR, 1) void gnn_mma(
    const float* __restrict__ uf,   const float* __restrict__ noise,
    const float* __restrict__ b_ue,
    const float* __restrict__ W_t,  const float* __restrict__ b_t,
    const float* __restrict__ caba, const float* __restrict__ cabs,
    const float* __restrict__ cabc, const float* __restrict__ cuba,
    const float* __restrict__ cubs, const float* __restrict__ cubc,
    const float* __restrict__ Wn,   const float* __restrict__ bn,
    float* __restrict__ out)
{
    extern __shared__ __align__(16) char sm[];
    const uint32_t smb = smem_u32(sm);
    const int tid = threadIdx.x;
    const int b   = blockIdx.x;

    float* vA   = (float*)(sm + OFF_VA);
    float* vU   = (float*)(sm + OFF_VU);
    float* vA2  = (float*)(sm + OFF_VA2);
    float* ant  = (float*)(sm + OFF_ANT);
    float* tmpA = (float*)(sm + OFF_TMA);
    float* tmpU = (float*)(sm + OFF_TMU);
    volatile int* flg = (volatile int*)(sm + OFF_FLG);

    if (tid < 8) flg[tid] = 0;

    // ---------- encoder ----------
    {
        const float* src = uf + (size_t)b * NU_ * HD;
        for (int idx = tid; idx < NU_ * HD; idx += NTHR) {
            const int m = idx >> 7, k = idx & 127;
            put_split(sm + OFF_SA, sm + OFF_SA_L, m, k, __ldg(src + idx));
        }
    }
    load_plane512(smb + OFF_B0, (const char*)&g_w[0][0][0], tid);
    load_plane512(smb + OFF_B1, (const char*)&g_w[0][1][0], tid);
    __syncthreads();   // staging + flag init visible
    blayer<32>(tid, smb + OFF_B0, smb + OFF_B1, nullptr, nullptr,
               smb + OFF_SA, smb + OFF_SA_L, sm + OFF_HU, sm + OFF_HU_L,
               b_ue, nullptr);

    // ant = relu(mean_u(hu) @ W_t + b_t)
    gmean(tid, sm + OFF_HU, sm + OFF_HU_L, NU_, vA);
    __syncthreads();
    if (tid < HD) {
        float acc = __ldg(b_t + tid);
        #pragma unroll 8
        for (int k = 0; k < HD; k++)
            acc += vA[k] * __ldg(W_t + k * HD + tid);
        ant[tid] = fmaxf(acc, 0.f);
    }
    __syncthreads();
    {   // HA = split(ant + noise)
        const float* np_ = noise + (size_t)b * NT_ * HD;
        for (int idx = tid; idx < NT_ * HD; idx += NTHR) {
            const int m = idx >> 7, f = idx & 127;
            put_split(sm + OFF_HA, sm + OFF_HA_L, m, f, ant[f] + __ldg(np_ + idx));
        }
    }
    __syncthreads();

    // ---------- round 1 + round 2 aggr/self: two concurrent chains ----------
    if (tid < 256)
        chainA(tid, sm, smb, caba, cabs, cabc, flg, vA, vA2, tmpA);
    else
        chainU(tid - 256, sm, smb, cuba, cubs, cubc, cabs, flg, vU, vA2, tmpU);
    __syncthreads();

    // ---------- round 2 comb: block-wide (2 x M64) ----------
    load_plane512(smb + OFF_B0, (const char*)&g_w[5][0][0], tid);   // w5 hi
    load_plane512(smb + OFF_B1, (const char*)&g_w[5][1][0], tid);   // w5 lo
    blayer<64>(tid, smb + OFF_B0, smb + OFF_B1,
               (const char*)&g_w[6][0][0], (const char*)&g_w[6][1][0],
               smb + OFF_SU, smb + OFF_SU_L, sm + OFF_SU, sm + OFF_SU_L,
               cabc, nullptr);
    blayer<64>(tid, smb + OFF_B0, smb + OFF_B1, nullptr, nullptr,
               smb + OFF_SU, smb + OFF_SU_L, sm + OFF_SU, sm + OFF_SU_L,
               cabc + 128, nullptr);

    // ---------- final projection + complex-pair normalization ----------
    float* TAf  = (float*)(sm + OFF_B0);          // [64][128] fp32
    float* WnS  = (float*)(sm + OFF_B1);          // [128][16]
    float* nbuf = (float*)(sm + OFF_B1 + 8192);   // [64][16]
    for (int idx = tid; idx < NT_ * HD; idx += NTHR) {
        const int m = idx >> 7, k = idx & 127;
        TAf[idx] = bget(sm + OFF_SU   + (size_t)m * P + k * 2) +
                   bget(sm + OFF_SU_L + (size_t)m * P + k * 2);
    }
    for (int i = tid; i < HD * 16; i += NTHR) WnS[i] = __ldg(Wn + i);
    __syncthreads();

    const int c  = tid & 15;
    const int rb = tid >> 4;      // 0..31
    float yv[2];
    #pragma unroll
    for (int i = 0; i < 2; i++) {
        const int r = rb + 32 * i;
        float acc = __ldg(bn + c);
        #pragma unroll 8
        for (int k = 0; k < HD; k++)
            acc += TAf[r * HD + k] * WnS[k * 16 + c];
        nbuf[r * 16 + c] = acc;
        yv[i] = acc;
    }
    __syncthreads();
    #pragma unroll
    for (int i = 0; i < 2; i++) {
        const int r  = rb + 32 * i;
        const int cp = c & 7;
        const float re  = nbuf[r * 16 + cp];
        const float im  = nbuf[r * 16 + cp + 8];
        const float mag = sqrtf(re * re + im * im);
        out[((size_t)b * NT_ + r) * 16 + c] = yv[i] / mag;
    }
}

// ---------------------------------------------------------------------
extern "C" void kernel_launch(void* const* d_in, const int* in_sizes, int n_in,
                              void* d_out, int out_size)
{
    (void)in_sizes; (void)n_in; (void)out_size;

    const float* user_feat = (const float*)d_in[0];
    const float* ant_noise = (const float*)d_in[1];
    // d_in[2..5]: edge indices — deterministic full bipartite per batch; unused.
    const float* W_ue = (const float*)d_in[6];
    const float* b_ue = (const float*)d_in[7];
    const float* W_t  = (const float*)d_in[8];
    const float* b_t  = (const float*)d_in[9];
    const float* caWa = (const float*)d_in[10];
    const float* caba = (const float*)d_in[11];
    const float* caWs = (const float*)d_in[12];
    const float* cabs = (const float*)d_in[13];
    const float* caWc = (const float*)d_in[14];
    const float* cabc = (const float*)d_in[15];
    const float* cuWa = (const float*)d_in[16];
    const float* cuba = (const float*)d_in[17];
    const float* cuWs = (const float*)d_in[18];
    const float* cubs = (const float*)d_in[19];
    const float* cuWc = (const float*)d_in[20];
    const float* cubc = (const float*)d_in[21];
    const float* Wn   = (const float*)d_in[22];
    const float* bn   = (const float*)d_in[23];
    float* out = (float*)d_out;

    static int init_done = 0;
    if (!init_done) {
        cudaFuncSetAttribute(gnn_mma,
                             cudaFuncAttributeMaxDynamicSharedMemorySize,
                             SM_BYTES);
        init_done = 1;
    }

    prep_w<<<13, 256>>>(W_ue, caWa, caWs, caWc, cuWa, cuWs, cuWc);
    gnn_mma<<<B_, NTHR, SM_BYTES>>>(
        user_feat, ant_noise, b_ue, W_t, b_t,
        caba, cabs, cabc, cuba, cubs, cubc,
        Wn, bn, out);
}

// round 15
// speedup vs baseline: 1.0426x; 1.0387x over previous
#include <cuda_runtime.h>
#include <cuda_bf16.h>
#include <math.h>
#include <stdint.h>

#define HD  128
#define B_  128
#define NU_ 32
#define NT_ 64
#define P   272          // tile pitch bytes (136 bf16): conflict-free ldmatrix
#define PE  136
#define NTHR 512
#define HALF 17408       // half weight plane (64 k-rows x 272 B)

// ---------------- packed weights in static global scratch ----------------
__device__ __align__(16) __nv_bfloat16 g_w[13][2][HD * PE];

// ---------------- smem layout (byte offsets, 16B aligned) ----------------
#define OFF_B0    0          // 34816 = 2 half-buffers (chain A)
#define OFF_B1    34816      // 34816 = 2 half-buffers (chain U)
#define OFF_HU    69632      // 32-row tile hi
#define OFF_HU_L  78336      // 32-row tile lo
#define OFF_HA    87040      // 64-row tile hi
#define OFF_HA_L  104448
#define OFF_SA    121856     // chain-A scratch 64-row hi/lo
#define OFF_SA_L  139264
#define OFF_SU    156672     // chain-U scratch 64-row hi/lo
#define OFF_SU_L  174080
#define OFF_VA    191488     // 128 fp32
#define OFF_VU    192000
#define OFF_VA2   192512
#define OFF_ANT   193024
#define OFF_FLG   193536     // 8 x int flags
#define OFF_TMA   193568     // 512: gmean partial (chain A)
#define OFF_TMU   194080     // 512: gmean partial (chain U)
#define OFF_SB    194592     // 6656: 13 x 128 fp32 staged biases
#define OFF_SBT   201248     // 512: b_t
#define OFF_SBN   201760     // 64: bn
#define SM_BYTES  201824

// ---------------- PTX helpers ----------------
__device__ __forceinline__ uint32_t smem_u32(const void* p) {
    uint32_t a;
    asm("{ .reg .u64 t; cvta.to.shared.u64 t, %1; cvt.u32.u64 %0, t; }"
        : "=r"(a) : "l"(p));
    return a;
}

#define LDSM4(d0, d1, d2, d3, a) \
    asm volatile("ldmatrix.sync.aligned.m8n8.x4.shared.b16 {%0,%1,%2,%3}, [%4];" \
                 : "=r"(d0), "=r"(d1), "=r"(d2), "=r"(d3) : "r"(a))
#define LDSM4T(d0, d1, d2, d3, a) \
    asm volatile("ldmatrix.sync.aligned.m8n8.x4.trans.shared.b16 {%0,%1,%2,%3}, [%4];" \
                 : "=r"(d0), "=r"(d1), "=r"(d2), "=r"(d3) : "r"(a))

#define MMA16816(c, a0, a1, a2, a3, b0, b1) \
    asm volatile("mma.sync.aligned.m16n8k16.row.col.f32.bf16.bf16.f32 " \
                 "{%0,%1,%2,%3}, {%4,%5,%6,%7}, {%8,%9}, {%0,%1,%2,%3};" \
                 : "+f"((c)[0]), "+f"((c)[1]), "+f"((c)[2]), "+f"((c)[3]) \
                 : "r"(a0), "r"(a1), "r"(a2), "r"(a3), "r"(b0), "r"(b1))

#define CP16(s, g) \
    asm volatile("cp.async.cg.shared.global [%0], [%1], 16;" :: "r"(s), "l"(g))
#define CP_COMMIT()  asm volatile("cp.async.commit_group;" ::: "memory")
#define CP_WAITG1()  asm volatile("cp.async.wait_group 1;" ::: "memory")
#define GBAR(id)     asm volatile("bar.sync %0, %1;" :: "r"(id), "r"(256) : "memory")

__device__ __forceinline__ float bget(const char* p) {
    return __bfloat162float(*(const __nv_bfloat16*)p);
}

__device__ __forceinline__ void put_split(char* hiT, char* loT, int m, int k, float v) {
    const __nv_bfloat16 h = __float2bfloat16(v);
    *(__nv_bfloat16*)(hiT + (size_t)m * P + k * 2) = h;
    *(__nv_bfloat16*)(loT + (size_t)m * P + k * 2) =
        __float2bfloat16(v - __bfloat162float(h));
}

__device__ __forceinline__ void raise_flag(volatile int* f) {
    __threadfence_block(); *f = 1;
}
__device__ __forceinline__ void wait_flag(volatile int* f) {
    while (*f == 0) {}
    __threadfence_block();
}

// ---------------- weight prep: fp32 W[k][n] -> padded bf16 hi/lo ----------------
__global__ __launch_bounds__(256) void prep_w(
    const float* __restrict__ ue,
    const float* __restrict__ caWa, const float* __restrict__ caWs,
    const float* __restrict__ caWc, const float* __restrict__ cuWa,
    const float* __restrict__ cuWs, const float* __restrict__ cuWc)
{
    const float* srcs[13] = {
        ue,
        caWa, caWa + 16384, caWs, caWs + 16384, caWc, caWc + 16384,
        cuWa, cuWa + 16384, cuWs, cuWs + 16384, cuWc, cuWc + 16384
    };
    const int w = blockIdx.x;
    const float* src = srcs[w];
    __nv_bfloat16* hi = &g_w[w][0][0];
    __nv_bfloat16* lo = &g_w[w][1][0];
    for (int idx = threadIdx.x; idx < HD * PE; idx += 256) {
        const int k = idx / PE;
        const int n = idx - k * PE;
        float v = (n < HD) ? __ldg(src + k * HD + n) : 0.f;
        const __nv_bfloat16 h = __float2bfloat16(v);
        hi[idx] = h;
        lo[idx] = __float2bfloat16(v - __bfloat162float(h));
    }
}

// ---------------- loaders ----------------
__device__ __forceinline__ void load_half256(uint32_t dst, const char* src, int gtid)
{
    #pragma unroll
    for (int i = 0; i < 5; i++) {
        const int e = gtid + i * 256;
        if (e < 1088) CP16(dst + e * 16, src + e * 16);
    }
    CP_COMMIT();
}

__device__ __forceinline__ void load_plane512(uint32_t dst, const char* src, int tid)
{
    #pragma unroll
    for (int i = 0; i < 5; i++) {
        const int e = tid + i * 512;
        if (e < 2176) CP16(dst + e * 16, src + e * 16);
    }
    CP_COMMIT();
}

// ---------------- full-plane passes (block-wide encoder layer) ----------------
template<int MR, int NW>
__device__ __forceinline__ void mma_hi(uint32_t aHi, uint32_t aLo, uint32_t wPlane,
                                       float* acc, int gtid)
{
    constexpr int MT  = MR / 16;
    constexpr int NB  = NW / MT;
    constexpr int NNT = 16 / NB;
    const int lane = gtid & 31;
    const int wp   = gtid >> 5;
    const int mtg  = wp / NB;
    const int nb   = (wp % NB) * (NNT * 8);
    const int r8  = (lane & 7) + ((lane >> 3) & 1) * 8;
    const int g16 = lane >> 4;
    const uint32_t aH = aHi + (uint32_t)(mtg * 16 + r8) * P + g16 * 16;
    const uint32_t aL = aLo + (uint32_t)(mtg * 16 + r8) * P + g16 * 16;
    const uint32_t bB = wPlane + (uint32_t)r8 * P + (uint32_t)(nb + g16 * 8) * 2;

    #pragma unroll
    for (int kt = 0; kt < 8; kt++) {
        uint32_t bf[NNT / 2][4];
        #pragma unroll
        for (int np = 0; np < NNT / 2; np++)
            LDSM4T(bf[np][0], bf[np][1], bf[np][2], bf[np][3],
                   bB + kt * (16 * P) + np * 32);
        uint32_t ah0, ah1, ah2, ah3, al0, al1, al2, al3;
        LDSM4(ah0, ah1, ah2, ah3, aH + kt * 32);
        LDSM4(al0, al1, al2, al3, aL + kt * 32);
        #pragma unroll
        for (int np = 0; np < NNT / 2; np++) {
            MMA16816(acc + (2 * np) * 4,     ah0, ah1, ah2, ah3, bf[np][0], bf[np][1]);
            MMA16816(acc + (2 * np + 1) * 4, ah0, ah1, ah2, ah3, bf[np][2], bf[np][3]);
        }
        #pragma unroll
        for (int np = 0; np < NNT / 2; np++) {
            MMA16816(acc + (2 * np) * 4,     al0, al1, al2, al3, bf[np][0], bf[np][1]);
            MMA16816(acc + (2 * np + 1) * 4, al0, al1, al2, al3, bf[np][2], bf[np][3]);
        }
    }
}

template<int MR, int NW>
__device__ __forceinline__ void mma_lo(uint32_t aHi, uint32_t wPlane,
                                       float* acc, int gtid)
{
    constexpr int MT  = MR / 16;
    constexpr int NB  = NW / MT;
    constexpr int NNT = 16 / NB;
    const int lane = gtid & 31;
    const int wp   = gtid >> 5;
    const int mtg  = wp / NB;
    const int nb   = (wp % NB) * (NNT * 8);
    const int r8  = (lane & 7) + ((lane >> 3) & 1) * 8;
    const int g16 = lane >> 4;
    const uint32_t aH = aHi + (uint32_t)(mtg * 16 + r8) * P + g16 * 16;
    const uint32_t bB = wPlane + (uint32_t)r8 * P + (uint32_t)(nb + g16 * 8) * 2;

    #pragma unroll
    for (int kt = 0; kt < 8; kt++) {
        uint32_t bf[NNT / 2][4];
        #pragma unroll
        for (int np = 0; np < NNT / 2; np++)
            LDSM4T(bf[np][0], bf[np][1], bf[np][2], bf[np][3],
                   bB + kt * (16 * P) + np * 32);
        uint32_t a0, a1, a2, a3;
        LDSM4(a0, a1, a2, a3, aH + kt * 32);
        #pragma unroll
        for (int np = 0; np < NNT / 2; np++) {
            MMA16816(acc + (2 * np) * 4,     a0, a1, a2, a3, bf[np][0], bf[np][1]);
            MMA16816(acc + (2 * np + 1) * 4, a0, a1, a2, a3, bf[np][2], bf[np][3]);
        }
    }
}

// ---------------- half-plane passes (chain layers, 8 warps) ----------------
template<int MR>
__device__ __forceinline__ void mma_half_hi(uint32_t aHi, uint32_t aLo, uint32_t wHalf,
                                            int kt0, float* acc, int gtid)
{
    constexpr int MT  = MR / 16;
    constexpr int NB  = 8 / MT;
    constexpr int NNT = 16 / NB;
    const int lane = gtid & 31;
    const int wp   = gtid >> 5;
    const int mtg  = wp / NB;
    const int nb   = (wp % NB) * (NNT * 8);
    const int r8  = (lane & 7) + ((lane >> 3) & 1) * 8;
    const int g16 = lane >> 4;
    const uint32_t aH = aHi + (uint32_t)(mtg * 16 + r8) * P + g16 * 16 + kt0 * 32;
    const uint32_t aL = aLo + (uint32_t)(mtg * 16 + r8) * P + g16 * 16 + kt0 * 32;
    const uint32_t bB = wHalf + (uint32_t)r8 * P + (uint32_t)(nb + g16 * 8) * 2;

    #pragma unroll
    for (int kt = 0; kt < 4; kt++) {
        uint32_t bf[NNT / 2][4];
        #pragma unroll
        for (int np = 0; np < NNT / 2; np++)
            LDSM4T(bf[np][0], bf[np][1], bf[np][2], bf[np][3],
                   bB + kt * (16 * P) + np * 32);
        uint32_t ah0, ah1, ah2, ah3, al0, al1, al2, al3;
        LDSM4(ah0, ah1, ah2, ah3, aH + kt * 32);
        LDSM4(al0, al1, al2, al3, aL + kt * 32);
        #pragma unroll
        for (int np = 0; np < NNT / 2; np++) {
            MMA16816(acc + (2 * np) * 4,     ah0, ah1, ah2, ah3, bf[np][0], bf[np][1]);
            MMA16816(acc + (2 * np + 1) * 4, ah0, ah1, ah2, ah3, bf[np][2], bf[np][3]);
        }
        #pragma unroll
        for (int np = 0; np < NNT / 2; np++) {
            MMA16816(acc + (2 * np) * 4,     al0, al1, al2, al3, bf[np][0], bf[np][1]);
            MMA16816(acc + (2 * np + 1) * 4, al0, al1, al2, al3, bf[np][2], bf[np][3]);
        }
    }
}

template<int MR>
__device__ __forceinline__ void mma_half_lo(uint32_t aHi, uint32_t wHalf,
                                            int kt0, float* acc, int gtid)
{
    constexpr int MT  = MR / 16;
    constexpr int NB  = 8 / MT;
    constexpr int NNT = 16 / NB;
    const int lane = gtid & 31;
    const int wp   = gtid >> 5;
    const int mtg  = wp / NB;
    const int nb   = (wp % NB) * (NNT * 8);
    const int r8  = (lane & 7) + ((lane >> 3) & 1) * 8;
    const int g16 = lane >> 4;
    const uint32_t aH = aHi + (uint32_t)(mtg * 16 + r8) * P + g16 * 16 + kt0 * 32;
    const uint32_t bB = wHalf + (uint32_t)r8 * P + (uint32_t)(nb + g16 * 8) * 2;

    #pragma unroll
    for (int kt = 0; kt < 4; kt++) {
        uint32_t bf[NNT / 2][4];
        #pragma unroll
        for (int np = 0; np < NNT / 2; np++)
            LDSM4T(bf[np][0], bf[np][1], bf[np][2], bf[np][3],
                   bB + kt * (16 * P) + np * 32);
        uint32_t a0, a1, a2, a3;
        LDSM4(a0, a1, a2, a3, aH + kt * 32);
        #pragma unroll
        for (int np = 0; np < NNT / 2; np++) {
            MMA16816(acc + (2 * np) * 4,     a0, a1, a2, a3, bf[np][0], bf[np][1]);
            MMA16816(acc + (2 * np + 1) * 4, a0, a1, a2, a3, bf[np][2], bf[np][3]);
        }
    }
}

// ---------------- epilogue: bias(smem) + relu (+vec) -> split bf16 tiles ----------------
template<int MR, int NW>
__device__ __forceinline__ void epilogue_t(const float* acc,
    char* oHi, char* oLo, const float* bias, const float* addv, int gtid)
{
    constexpr int MT  = MR / 16;
    constexpr int NB  = NW / MT;
    constexpr int NNT = 16 / NB;
    const int lane = gtid & 31;
    const int wp   = gtid >> 5;
    const int mtg  = wp / NB;
    const int nb   = (wp % NB) * (NNT * 8);
    const int r0   = mtg * 16 + (lane >> 2);

    #pragma unroll
    for (int t = 0; t < NNT; t++) {
        const int c0 = nb + t * 8 + (lane & 3) * 2;
        const float b0v = bias[c0], b1v = bias[c0 + 1];
        float av0 = 0.f, av1 = 0.f;
        if (addv) { av0 = addv[c0]; av1 = addv[c0 + 1]; }
        const float y0 = fmaxf(acc[t * 4 + 0] + b0v, 0.f) + av0;
        const float y1 = fmaxf(acc[t * 4 + 1] + b1v, 0.f) + av1;
        const float y2 = fmaxf(acc[t * 4 + 2] + b0v, 0.f) + av0;
        const float y3 = fmaxf(acc[t * 4 + 3] + b1v, 0.f) + av1;

        __nv_bfloat162 h01, h23, l01, l23;
        h01.x = __float2bfloat16(y0); h01.y = __float2bfloat16(y1);
        h23.x = __float2bfloat16(y2); h23.y = __float2bfloat16(y3);
        l01.x = __float2bfloat16(y0 - __bfloat162float(h01.x));
        l01.y = __float2bfloat16(y1 - __bfloat162float(h01.y));
        l23.x = __float2bfloat16(y2 - __bfloat162float(h23.x));
        l23.y = __float2bfloat16(y3 - __bfloat162float(h23.y));

        *(__nv_bfloat162*)(oHi + (size_t)r0 * P + c0 * 2)       = h01;
        *(__nv_bfloat162*)(oHi + (size_t)(r0 + 8) * P + c0 * 2) = h23;
        *(__nv_bfloat162*)(oLo + (size_t)r0 * P + c0 * 2)       = l01;
        *(__nv_bfloat162*)(oLo + (size_t)(r0 + 8) * P + c0 * 2) = l23;
    }
}

// ---------------- chain (8-warp) layer with half-plane pipelining ----------------
template<int MR>
__device__ __forceinline__ void glayer(
    int barid, int gtid, int widx, int widx_next,
    uint32_t aHi, uint32_t aLo, char* oHi, char* oLo,
    const float* bias, const float* addv,
    volatile int* waitflag, volatile int* raiseflag,
    uint32_t buf0, uint32_t buf1)
{
    constexpr int NNT = 16 / (8 / (MR / 16));
    float acc[NNT * 4];
    #pragma unroll
    for (int i = 0; i < NNT * 4; i++) acc[i] = 0.f;

    const char* wlo = (const char*)&g_w[widx][1][0];

    CP_WAITG1(); GBAR(barid);                        // hi.h0 ready
    mma_half_hi<MR>(aHi, aLo, buf0, 0, acc, gtid);
    GBAR(barid);
    load_half256(buf0, wlo, gtid);
    CP_WAITG1(); GBAR(barid);                        // hi.h1 ready
    mma_half_hi<MR>(aHi, aLo, buf1, 4, acc, gtid);
    GBAR(barid);
    load_half256(buf1, wlo + HALF, gtid);
    CP_WAITG1(); GBAR(barid);                        // lo.h0 ready
    mma_half_lo<MR>(aHi, buf0, 0, acc, gtid);
    GBAR(barid);
    if (widx_next >= 0)
        load_half256(buf0, (const char*)&g_w[widx_next][0][0], gtid);
    else CP_COMMIT();
    CP_WAITG1(); GBAR(barid);                        // lo.h1 ready
    mma_half_lo<MR>(aHi, buf1, 4, acc, gtid);
    GBAR(barid);                                     // all A/W reads done
    if (widx_next >= 0)
        load_half256(buf1, (const char*)&g_w[widx_next][0][0] + HALF, gtid);
    else CP_COMMIT();

    if (raiseflag) raise_flag(raiseflag);
    if (waitflag)  wait_flag(waitflag);
    epilogue_t<MR, 8>(acc, oHi, oLo, bias, addv, gtid);
    GBAR(barid);                                     // outputs visible in crew
}

// crew-parallel column mean of hi+lo tile -> vec[128]
__device__ __forceinline__ void gmean2(int barid, int gtid,
                                       const char* tHi, const char* tLo,
                                       int nrows, float* vec, float* tmp)
{
    const int c = gtid & 127;
    const char* t = (gtid < 128) ? tHi : tLo;
    float s = 0.f;
    for (int m = 0; m < nrows; m++)
        s += bget(t + (size_t)m * P + c * 2);
    if (gtid < 128) vec[c] = s; else tmp[c] = s;
    GBAR(barid);
    if (gtid < 128) vec[c] = (vec[c] + tmp[c]) / (float)nrows;
    GBAR(barid);
}

// block-serial column mean (encoder)
__device__ __forceinline__ void gmean(int gtid, const char* tHi, const char* tLo,
                                      int nrows, float* vec)
{
    if (gtid < HD) {
        float s = 0.f;
        for (int m = 0; m < nrows; m++)
            s += bget(tHi + (size_t)m * P + gtid * 2) +
                 bget(tLo + (size_t)m * P + gtid * 2);
        vec[gtid] = s / (float)nrows;
    }
}

// ---------------- block (16-warp) pipelined layer (encoder only) ----------------
template<int MR>
__device__ __forceinline__ void blayer(
    int tid, uint32_t bufHi, uint32_t bufLo,
    const char* pfHi, const char* pfLo,
    uint32_t aHi, uint32_t aLo, char* oHi, char* oLo,
    const float* bias, const float* addv)
{
    constexpr int NNT = 16 / (16 / (MR / 16));
    float acc[NNT * 4];
    #pragma unroll
    for (int i = 0; i < NNT * 4; i++) acc[i] = 0.f;

    CP_WAITG1(); __syncthreads();
    mma_hi<MR, 16>(aHi, aLo, bufHi, acc, tid);
    __syncthreads();
    if (pfHi) load_plane512(bufHi, pfHi, tid); else CP_COMMIT();
    CP_WAITG1(); __syncthreads();
    mma_lo<MR, 16>(aHi, bufLo, acc, tid);
    __syncthreads();
    if (pfLo) load_plane512(bufLo, pfLo, tid); else CP_COMMIT();
    epilogue_t<MR, 16>(acc, oHi, oLo, bias, addv, tid);
    __syncthreads();
}

// ---------------- chain runners ----------------
// flags: f[0]=chainA read old HU done; f[1]=chainU read old HA done;
//        f[2]=vA2 ready; f[3]=HA_new ready; f[4]=HU_new ready; f[5]=SU(comb input) ready
__device__ void chainA(int gtid, char* sm, uint32_t smb, const float* sb,
                       volatile int* f, float* vA, float* vA2, float* tmpA)
{
    const uint32_t b0 = smb + OFF_B0;
    const uint32_t b1 = smb + OFF_B0 + HALF;
    load_half256(b0, (const char*)&g_w[1][0][0], gtid);
    load_half256(b1, (const char*)&g_w[1][0][0] + HALF, gtid);

    // round 1: na chain
    glayer<32>(1, gtid, 1, 2, smb + OFF_HU, smb + OFF_HU_L,
               sm + OFF_SA, sm + OFF_SA_L, sb + 1 * HD, nullptr, nullptr, f + 0, b0, b1);
    glayer<32>(1, gtid, 2, 3, smb + OFF_SA, smb + OFF_SA_L,
               sm + OFF_SA, sm + OFF_SA_L, sb + 2 * HD, nullptr, nullptr, nullptr, b0, b1);
    gmean2(1, gtid, sm + OFF_SA, sm + OFF_SA_L, NU_, vA, tmpA);
    glayer<64>(1, gtid, 3, 4, smb + OFF_HA, smb + OFF_HA_L,
               sm + OFF_SA, sm + OFF_SA_L, sb + 3 * HD, nullptr, nullptr, nullptr, b0, b1);
    glayer<64>(1, gtid, 4, 5, smb + OFF_SA, smb + OFF_SA_L,
               sm + OFF_SA, sm + OFF_SA_L, sb + 4 * HD, vA, nullptr, nullptr, b0, b1);
    glayer<64>(1, gtid, 5, 6, smb + OFF_SA, smb + OFF_SA_L,
               sm + OFF_SA, sm + OFF_SA_L, sb + 5 * HD, nullptr, nullptr, nullptr, b0, b1);
    glayer<64>(1, gtid, 6, 1, smb + OFF_SA, smb + OFF_SA_L,
               sm + OFF_HA, sm + OFF_HA_L, sb + 6 * HD, nullptr, f + 1, nullptr, b0, b1);
    raise_flag(f + 3);                       // HA_new ready

    // round 2: aggr MLP on hu_new (produced by chainU)
    wait_flag(f + 4);                        // HU_new ready
    glayer<32>(1, gtid, 1, 2, smb + OFF_HU, smb + OFF_HU_L,
               sm + OFF_SA, sm + OFF_SA_L, sb + 1 * HD, nullptr, nullptr, nullptr, b0, b1);
    glayer<32>(1, gtid, 2, 5, smb + OFF_SA, smb + OFF_SA_L,
               sm + OFF_SA, sm + OFF_SA_L, sb + 2 * HD, nullptr, nullptr, nullptr, b0, b1);
    gmean2(1, gtid, sm + OFF_SA, sm + OFF_SA_L, NU_, vA2, tmpA);
    raise_flag(f + 2);                       // vA2 ready

    // round 2 comb: rows 0..31 (w5 hi halves already prefetched by prev glayer)
    wait_flag(f + 5);                        // SU (self2 output) ready
    glayer<32>(1, gtid, 5, 6, smb + OFF_SU, smb + OFF_SU_L,
               sm + OFF_SU, sm + OFF_SU_L, sb + 5 * HD, nullptr, nullptr, nullptr, b0, b1);
    glayer<32>(1, gtid, 6, -1, smb + OFF_SU, smb + OFF_SU_L,
               sm + OFF_SU, sm + OFF_SU_L, sb + 6 * HD, nullptr, nullptr, nullptr, b0, b1);
}

__device__ void chainU(int gtid, char* sm, uint32_t smb, const float* sb,
                       volatile int* f, float* vU, float* vA2, float* tmpU)
{
    const uint32_t b0 = smb + OFF_B1;
    const uint32_t b1 = smb + OFF_B1 + HALF;
    load_half256(b0, (const char*)&g_w[7][0][0], gtid);
    load_half256(b1, (const char*)&g_w[7][0][0] + HALF, gtid);

    // round 1: nu chain
    glayer<64>(2, gtid, 7, 8, smb + OFF_HA, smb + OFF_HA_L,
               sm + OFF_SU, sm + OFF_SU_L, sb + 7 * HD, nullptr, nullptr, f + 1, b0, b1);
    glayer<64>(2, gtid, 8, 9, smb + OFF_SU, smb + OFF_SU_L,
               sm + OFF_SU, sm + OFF_SU_L, sb + 8 * HD, nullptr, nullptr, nullptr, b0, b1);
    gmean2(2, gtid, sm + OFF_SU, sm + OFF_SU_L, NT_, vU, tmpU);
    glayer<32>(2, gtid, 9, 10, smb + OFF_HU, smb + OFF_HU_L,
               sm + OFF_SU, sm + OFF_SU_L, sb + 9 * HD, nullptr, nullptr, nullptr, b0, b1);
    glayer<32>(2, gtid, 10, 11, smb + OFF_SU, smb + OFF_SU_L,
               sm + OFF_SU, sm + OFF_SU_L, sb + 10 * HD, vU, nullptr, nullptr, b0, b1);
    glayer<32>(2, gtid, 11, 12, smb + OFF_SU, smb + OFF_SU_L,
               sm + OFF_SU, sm + OFF_SU_L, sb + 11 * HD, nullptr, nullptr, nullptr, b0, b1);
    glayer<32>(2, gtid, 12, 3, smb + OFF_SU, smb + OFF_SU_L,
               sm + OFF_HU, sm + OFF_HU_L, sb + 12 * HD, nullptr, f + 0, nullptr, b0, b1);
    raise_flag(f + 4);                       // HU_new ready

    // round 2: self MLP on ha_new (produced by chainA)
    wait_flag(f + 3);                        // HA_new ready
    glayer<64>(2, gtid, 3, 4, smb + OFF_HA, smb + OFF_HA_L,
               sm + OFF_SU, sm + OFF_SU_L, sb + 3 * HD, nullptr, nullptr, nullptr, b0, b1);
    glayer<64>(2, gtid, 4, 5, smb + OFF_SU, smb + OFF_SU_L,
               sm + OFF_SU, sm + OFF_SU_L, sb + 4 * HD, vA2, f + 2, nullptr, b0, b1);
    raise_flag(f + 5);                       // SU ready for comb

    // round 2 comb: rows 32..63 (w5 hi halves prefetched by prev glayer)
    glayer<32>(2, gtid, 5, 6, smb + OFF_SU + 32 * P, smb + OFF_SU_L + 32 * P,
               sm + OFF_SU + 32 * P, sm + OFF_SU_L + 32 * P,
               sb + 5 * HD, nullptr, nullptr, nullptr, b0, b1);
    glayer<32>(2, gtid, 6, -1, smb + OFF_SU + 32 * P, smb + OFF_SU_L + 32 * P,
               sm + OFF_SU + 32 * P, sm + OFF_SU_L + 32 * P,
               sb + 6 * HD, nullptr, nullptr, nullptr, b0, b1);
}

// ---------------- main fused kernel ----------------
__global__ __launch_bounds__(NTHR, 1) void gnn_mma(
    const float* __restrict__ uf,   const float* __restrict__ noise,
    const float* __restrict__ b_ue,
    const float* __restrict__ W_t,  const float* __restrict__ b_t,
    const float* __restrict__ caba, const float* __restrict__ cabs,
    const float* __restrict__ cabc, const float* __restrict__ cuba,
    const float* __restrict__ cubs, const float* __restrict__ cubc,
    const float* __restrict__ Wn,   const float* __restrict__ bn,
    float* __restrict__ out)
{
    extern __shared__ __align__(16) char sm[];
    const uint32_t smb = smem_u32(sm);
    const int tid = threadIdx.x;
    const int b   = blockIdx.x;

    float* vA   = (float*)(sm + OFF_VA);
    float* vU   = (float*)(sm + OFF_VU);
    float* vA2  = (float*)(sm + OFF_VA2);
    float* ant  = (float*)(sm + OFF_ANT);
    float* tmpA = (float*)(sm + OFF_TMA);
    float* tmpU = (float*)(sm + OFF_TMU);
    float* sb   = (float*)(sm + OFF_SB);
    float* sbt  = (float*)(sm + OFF_SBT);
    float* sbn  = (float*)(sm + OFF_SBN);
    volatile int* flg = (volatile int*)(sm + OFF_FLG);

    if (tid < 8) flg[tid] = 0;

    // ---------- stage all biases into smem ----------
    {
        const float* bsrc[13] = {
            b_ue, caba, caba + 128, cabs, cabs + 128, cabc, cabc + 128,
            cuba, cuba + 128, cubs, cubs + 128, cubc, cubc + 128
        };
        for (int i = tid; i < 13 * HD; i += NTHR)
            sb[i] = __ldg(bsrc[i >> 7] + (i & 127));
        if (tid < HD) sbt[tid] = __ldg(b_t + tid);
        if (tid < 16) sbn[tid] = __ldg(bn + tid);
    }

    // ---------- encoder ----------
    {
        const float* src = uf + (size_t)b * NU_ * HD;
        for (int idx = tid; idx < NU_ * HD; idx += NTHR) {
            const int m = idx >> 7, k = idx & 127;
            put_split(sm + OFF_SA, sm + OFF_SA_L, m, k, __ldg(src + idx));
        }
    }
    load_plane512(smb + OFF_B0, (const char*)&g_w[0][0][0], tid);
    load_plane512(smb + OFF_B1, (const char*)&g_w[0][1][0], tid);
    __syncthreads();   // staging + flags + biases visible
    blayer<32>(tid, smb + OFF_B0, smb + OFF_B1, nullptr, nullptr,
               smb + OFF_SA, smb + OFF_SA_L, sm + OFF_HU, sm + OFF_HU_L,
               sb, nullptr);

    // ant = relu(mean_u(hu) @ W_t + b_t), matvec parallelized over 512 threads
    gmean(tid, sm + OFF_HU, sm + OFF_HU_L, NU_, vA);
    __syncthreads();
    {
        const int h = tid & 127, q = tid >> 7;     // k-quarter per thread group
        float s = 0.f;
        const float* wt = W_t + (size_t)(q * 32) * HD + h;
        #pragma unroll 8
        for (int k = 0; k < 32; k++) s += vA[q * 32 + k] * __ldg(wt + (size_t)k * HD);
        ((float*)(sm + OFF_B0))[q * HD + h] = s;
    }
    __syncthreads();
    if (tid < HD) {
        const float* pp = (const float*)(sm + OFF_B0);
        const float acc = sbt[tid] + pp[tid] + pp[HD + tid] +
                          pp[2 * HD + tid] + pp[3 * HD + tid];
        ant[tid] = fmaxf(acc, 0.f);
    }
    __syncthreads();
    {   // HA = split(ant + noise)
        const float* np_ = noise + (size_t)b * NT_ * HD;
        for (int idx = tid; idx < NT_ * HD; idx += NTHR) {
            const int m = idx >> 7, f = idx & 127;
            put_split(sm + OFF_HA, sm + OFF_HA_L, m, f, ant[f] + __ldg(np_ + idx));
        }
    }
    __syncthreads();

    // ---------- rounds 1+2: two concurrent chains (incl. row-split comb) ----------
    if (tid < 256)
        chainA(tid, sm, smb, sb, flg, vA, vA2, tmpA);
    else
        chainU(tid - 256, sm, smb, sb, flg, vU, vA2, tmpU);
    __syncthreads();

    // ---------- final projection + complex-pair normalization ----------
    float* TAf  = (float*)(sm + OFF_B0);          // [64][128] fp32
    float* WnS  = (float*)(sm + OFF_B1);          // [128][16]
    float* nbuf = (float*)(sm + OFF_B1 + 8192);   // [64][16]
    for (int idx = tid; idx < NT_ * HD; idx += NTHR) {
        const int m = idx >> 7, k = idx & 127;
        TAf[idx] = bget(sm + OFF_SU   + (size_t)m * P + k * 2) +
                   bget(sm + OFF_SU_L + (size_t)m * P + k * 2);
    }
    for (int i = tid; i < HD * 16; i += NTHR) WnS[i] = __ldg(Wn + i);
    __syncthreads();

    const int c  = tid & 15;
    const int rb = tid >> 4;      // 0..31
    float yv[2];
    #pragma unroll
    for (int i = 0; i < 2; i++) {
        const int r = rb + 32 * i;
        float acc = sbn[c];
        #pragma unroll 8
        for (int k = 0; k < HD; k++)
            acc += TAf[r * HD + k] * WnS[k * 16 + c];
        nbuf[r * 16 + c] = acc;
        yv[i] = acc;
    }
    __syncthreads();
    #pragma unroll
    for (int i = 0; i < 2; i++) {
        const int r  = rb + 32 * i;
        const int cp = c & 7;
        const float re  = nbuf[r * 16 + cp];
        const float im  = nbuf[r * 16 + cp + 8];
        const float mag = sqrtf(re * re + im * im);
        out[((size_t)b * NT_ + r) * 16 + c] = yv[i] / mag;
    }
}

// ---------------------------------------------------------------------
extern "C" void kernel_launch(void* const* d_in, const int* in_sizes, int n_in,
                              void* d_out, int out_size)
{
    (void)in_sizes; (void)n_in; (void)out_size;

    const float* user_feat = (const float*)d_in[0];
    const float* ant_noise = (const float*)d_in[1];
    // d_in[2..5]: edge indices — deterministic full bipartite per batch; unused.
    const float* W_ue = (const float*)d_in[6];
    const float* b_ue = (const float*)d_in[7];
    const float* W_t  = (const float*)d_in[8];
    const float* b_t  = (const float*)d_in[9];
    const float* caWa = (const float*)d_in[10];
    const float* caba = (const float*)d_in[11];
    const float* caWs = (const float*)d_in[12];
    const float* cabs = (const float*)d_in[13];
    const float* caWc = (const float*)d_in[14];
    const float* cabc = (const float*)d_in[15];
    const float* cuWa = (const float*)d_in[16];
    const float* cuba = (const float*)d_in[17];
    const float* cuWs = (const float*)d_in[18];
    const float* cubs = (const float*)d_in[19];
    const float* cuWc = (const float*)d_in[20];
    const float* cubc = (const float*)d_in[21];
    const float* Wn   = (const float*)d_in[22];
    const float* bn   = (const float*)d_in[23];
    float* out = (float*)d_out;

    static int init_done = 0;
    if (!init_done) {
        cudaFuncSetAttribute(gnn_mma,
                             cudaFuncAttributeMaxDynamicSharedMemorySize,
                             SM_BYTES);
        init_done = 1;
    }

    prep_w<<<13, 256>>>(W_ue, caWa, caWs, caWc, cuWa, cuWs, cuWc);
    gnn_mma<<<B_, NTHR, SM_BYTES>>>(
        user_feat, ant_noise, b_ue, W_t, b_t,
        caba, cabs, cabc, cuba, cubs, cubc,
        Wn, bn, out);
}